// round 10
// baseline (speedup 1.0000x reference)
#include <cuda_runtime.h>
#include <cuda_fp16.h>
#include <math.h>
#include <cstdint>

// ===========================================================================
//   conv1 -> conv2 (implicit GEMM M=20000,N=256,K=9216)
//   conv3 (K=512) -> u -> fused routing (on-the-fly u_hat)
//   GEMMs: single-term fp16 mma.sync, fp32 accum.
//   Grid 296: 33xM160 + 115xM128 exact tiles (zero redundancy), all resident.
// ===========================================================================

__device__ __align__(16) __half g_xpf[32 * 30 * 30 * 256];   // padded conv1 (fp16)
__device__ __align__(16) __half g_zc[20000 * 512];           // [conv1|conv2] fp16
__device__ __align__(16) __half g_w2f[256 * 9216];
__device__ __align__(16) __half g_w3f[256 * 512];
__device__ float g_c3[20000 * 256];
__device__ float g_u[20000 * 256];       // u[n][b*8+o]
__device__ float g_S0[32 * 128];
__device__ float g_S1[32 * 128];
__device__ float g_S2[32 * 128];
__device__ float g_v0[32 * 128];
__device__ float g_v1[32 * 128];

// ---------------------------------------------------------------------------
__global__ void k_zero_all() {
    int i = blockIdx.x * 256 + threadIdx.x;
    if (i < 3686400) ((uint32_t*)g_xpf)[i] = 0u;    // 7372800 halves
    if (i < 32 * 128) { g_S0[i] = 0.f; g_S1[i] = 0.f; g_S2[i] = 0.f; }
}

// conv1: block = (batch, 5 output rows). w1 taps in registers, x tile in smem.
__global__ void __launch_bounds__(256) k_conv1(const float* __restrict__ x,
                                               const float* __restrict__ w1,
                                               const float* __restrict__ b1) {
    __shared__ float xs[14 * 54];
    int b = blockIdx.x;
    int r0 = blockIdx.y * 5;
    int t = threadIdx.x;

    for (int idx = t; idx < 14 * 54; idx += 256) {
        int row = idx / 54, col = idx % 54;
        xs[idx] = x[b * 2916 + (2 * r0 + row) * 54 + col];
    }
    float wr[36];
#pragma unroll
    for (int j = 0; j < 36; j++) wr[j] = __ldg(&w1[t * 36 + j]);
    float bias = __ldg(&b1[t]);
    __syncthreads();

    for (int pr = 0; pr < 5; pr++) {
        int oh = r0 + pr;
#pragma unroll 5
        for (int ow = 0; ow < 25; ow++) {
            float acc = bias;
#pragma unroll
            for (int kh = 0; kh < 6; kh++)
#pragma unroll
                for (int kw = 0; kw < 6; kw++)
                    acc += xs[(2 * pr + kh) * 54 + 2 * ow + kw] * wr[kh * 6 + kw];
            acc = fmaxf(acc, 0.f);
            __half h = __float2half_rn(acc);
            g_xpf[((b * 30 + oh + 2) * 30 + (ow + 2)) * 256 + t] = h;
            g_zc[(b * 625 + oh * 25 + ow) * 512 + t] = h;
        }
    }
}

// fused weight prep: blocks 0..255 -> conv2 w transpose, 256..767 -> conv3 w
__global__ void k_prep_w(const float* __restrict__ w2,
                         const float* __restrict__ w3) {
    __shared__ float s[256 * 37];
    int bx = blockIdx.x;
    int t = threadIdx.x;
    if (bx < 256) {
        int oc = bx;
        for (int j = 0; j < 36; j++) {
            int idx = t + 256 * j;
            int ic = idx / 36, khw = idx % 36;
            s[ic * 37 + khw] = w2[oc * 9216 + idx];
        }
        __syncthreads();
        for (int j = 0; j < 36; j++) {
            int o = t + 256 * j;
            int khw = o >> 8, ic = o & 255;
            g_w2f[oc * 9216 + o] = __float2half_rn(s[ic * 37 + khw]);
        }
    } else {
        int i = (bx - 256) * 256 + t;
        if (i < 131072) g_w3f[i] = __float2half_rn(w3[i]);
    }
}

// ---------------------------------------------------------------------------
// GEMM helpers
// ---------------------------------------------------------------------------
__device__ __forceinline__ uint32_t smem_u32(const void* p) {
    uint32_t a;
    asm("{ .reg .u64 t; cvta.to.shared.u64 t, %1; cvt.u32.u64 %0, t; }" : "=r"(a) : "l"(p));
    return a;
}
__device__ __forceinline__ void cpa16(uint32_t d, const void* g) {
    asm volatile("cp.async.cg.shared.global [%0], [%1], 16;" :: "r"(d), "l"(g) : "memory");
}
#define CP_COMMIT() asm volatile("cp.async.commit_group;" ::: "memory")
#define CP_WAIT(n)  asm volatile("cp.async.wait_group %0;" :: "n"(n) : "memory")

__device__ __forceinline__ void ldsm4(uint32_t& r0, uint32_t& r1, uint32_t& r2, uint32_t& r3,
                                      uint32_t a) {
    asm volatile("ldmatrix.sync.aligned.m8n8.x4.shared.b16 {%0,%1,%2,%3}, [%4];"
                 : "=r"(r0), "=r"(r1), "=r"(r2), "=r"(r3) : "r"(a));
}
__device__ __forceinline__ void mma16816(float& c0, float& c1, float& c2, float& c3,
                                         uint32_t a0, uint32_t a1, uint32_t a2, uint32_t a3,
                                         uint32_t b0, uint32_t b1) {
    asm volatile("mma.sync.aligned.m16n8k16.row.col.f32.f16.f16.f32 "
                 "{%0,%1,%2,%3}, {%4,%5,%6,%7}, {%8,%9}, {%0,%1,%2,%3};"
                 : "+f"(c0), "+f"(c1), "+f"(c2), "+f"(c3)
                 : "r"(a0), "r"(a1), "r"(a2), "r"(a3), "r"(b0), "r"(b1));
}

__device__ __forceinline__ uint32_t swaddr(uint32_t region, int row, int chunk) {
    return region + (uint32_t)row * 64u + (uint32_t)((chunk ^ ((row >> 1) & 3)) << 4);
}

// stage: A up to 160x32 fp16 (10240B) | B 128x32 (8192B)
#define OFF_B  10240
#define STGSZ  18432
#define SMEM_GEMM (3 * STGSZ)

// Tile map: bid%148 = s, bid/148 = wave.
//  s<66 && wave==0 -> M160 tile (33 m-positions x 2 n-halves), m0 = (s>>1)*160
//  else M128 tile j: wave0 j=s-66, wave1 j=82+s; m0 = 5280+(j>>1)*128
// Covers [0,20000) exactly once. bids i and i+148 share an SM -> each SM gets
// at most one M160 tile (work 288 vs uniform-overlap 320).
template<int MODE>
__global__ void __launch_bounds__(256, 2) k_gemm2(const float* __restrict__ bias) {
    constexpr int K = (MODE == 0) ? 9216 : 512;
    constexpr int S = K / 32;
    extern __shared__ char sm[];
    __shared__ int s_rowbase[160];
    const uint32_t sbase = smem_u32(sm);
    const int tid = threadIdx.x;

    int sslot = blockIdx.x % 148, wave = blockIdx.x / 148;
    int MI, m0, n0;
    if (sslot < 66 && wave == 0) {
        MI = 5; m0 = (sslot >> 1) * 160; n0 = (sslot & 1) * 128;
    } else {
        int j = (wave == 0) ? (sslot - 66) : (82 + sslot);
        MI = 4; m0 = 5280 + (j >> 1) * 128; n0 = (j & 1) * 128;
    }
    const int achunks = MI * 128;          // A 16B-chunks (rows*4)

    if (MODE == 0 && tid < 160) {
        int m = min(m0 + tid, 19999);
        int b = m / 625, p = m % 625, oh = p / 25, ow = p % 25;
        s_rowbase[tid] = ((b * 30 + oh) * 30 + ow) * 256;
    }
    __syncthreads();

    const __half* WH = (MODE == 0) ? g_w2f : g_w3f;

    auto issue = [&](int s) {
        int k0 = s * 32;
        uint32_t dbase = sbase + (s % 3) * STGSZ;
        int aoff = 0;
        if (MODE == 0) {
            int khw = k0 >> 8;
            int kh = khw / 6, kw = khw - kh * 6;
            aoff = (kh * 30 + kw) * 256 + (k0 & 255);
        }
#pragma unroll
        for (int j = 0; j < 5; j++) {
            int c = tid + j * 256;
            if (c < achunks) {                   // A region
                int row = c >> 2, kc = c & 3;
                const __half* src;
                if (MODE == 0) src = g_xpf + s_rowbase[row] + aoff + kc * 8;
                else           src = g_zc + (size_t)(m0 + row) * 512 + k0 + kc * 8;
                cpa16(swaddr(dbase, row, kc), src);
            } else if (c < achunks + 512) {      // B
                int c2 = c - achunks;
                int row = c2 >> 2, kc = c2 & 3;
                cpa16(swaddr(dbase + OFF_B, row, kc),
                      WH + (size_t)(n0 + row) * K + k0 + kc * 8);
            }
        }
        CP_COMMIT();
    };

    const int lane = tid & 31, wid = tid >> 5;
    const int wm = (wid & 1) * (MI * 16), wn = (wid >> 1) * 32;
    const int grp = lane >> 2, q = lane & 3;
    const int lrow = lane & 15, lk = lane >> 4;

    float acc[5][4][4];
#pragma unroll
    for (int i = 0; i < 5; i++)
#pragma unroll
        for (int j = 0; j < 4; j++)
#pragma unroll
            for (int c = 0; c < 4; c++) acc[i][j][c] = 0.f;

    issue(0);
    issue(1);

    for (int s = 0; s < S; s++) {
        if (s < S - 1) CP_WAIT(1); else CP_WAIT(0);
        __syncthreads();
        if (s + 2 < S) issue(s + 2);

        uint32_t Ar = sbase + (s % 3) * STGSZ;
        uint32_t Br = Ar + OFF_B;

#pragma unroll
        for (int kk = 0; kk < 2; kk++) {
            int ckc = kk * 2 + lk;
            uint32_t bh[4][2];
#pragma unroll
            for (int p2 = 0; p2 < 2; p2++) {
                int row = wn + p2 * 16 + lrow;
                uint32_t r0, r1, r2, r3;
                ldsm4(r0, r1, r2, r3, swaddr(Br, row, ckc));
                bh[2 * p2][0] = r0; bh[2 * p2][1] = r2;
                bh[2 * p2 + 1][0] = r1; bh[2 * p2 + 1][1] = r3;
            }
#pragma unroll
            for (int mi = 0; mi < 4; mi++) {
                uint32_t a0, a1, a2, a3;
                ldsm4(a0, a1, a2, a3, swaddr(Ar, wm + mi * 16 + lrow, ckc));
#pragma unroll
                for (int ni = 0; ni < 4; ni++) {
                    float* c = acc[mi][ni];
                    mma16816(c[0], c[1], c[2], c[3], a0, a1, a2, a3,
                             bh[ni][0], bh[ni][1]);
                }
            }
            if (MI == 5) {
                uint32_t a0, a1, a2, a3;
                ldsm4(a0, a1, a2, a3, swaddr(Ar, wm + 64 + lrow, ckc));
#pragma unroll
                for (int ni = 0; ni < 4; ni++) {
                    float* c = acc[4][ni];
                    mma16816(c[0], c[1], c[2], c[3], a0, a1, a2, a3,
                             bh[ni][0], bh[ni][1]);
                }
            }
        }
    }
    __syncthreads();

    // epilogue (exact tiles, every row written once)
#pragma unroll
    for (int mi = 0; mi < 5; mi++) {
        if (mi == 4 && MI != 5) break;
#pragma unroll
        for (int ni = 0; ni < 4; ni++) {
            int col = n0 + wn + ni * 8 + 2 * q;
            float bb0 = bias[col], bb1 = bias[col + 1];
            int row0 = m0 + wm + mi * 16 + grp;
            int row1 = row0 + 8;
            float* c = acc[mi][ni];
            if (MODE == 0) {
                float v0 = fmaxf(c[0] + bb0, 0.f), v1 = fmaxf(c[1] + bb1, 0.f);
                __half2 h01; h01.x = __float2half_rn(v0); h01.y = __float2half_rn(v1);
                *(__half2*)&g_zc[(size_t)row0 * 512 + 256 + col] = h01;
                float v2 = fmaxf(c[2] + bb0, 0.f), v3 = fmaxf(c[3] + bb1, 0.f);
                __half2 h23; h23.x = __float2half_rn(v2); h23.y = __float2half_rn(v3);
                *(__half2*)&g_zc[(size_t)row1 * 512 + 256 + col] = h23;
            } else {
                *(float2*)&g_c3[(size_t)row0 * 256 + col] = make_float2(c[0] + bb0, c[1] + bb1);
                *(float2*)&g_c3[(size_t)row1 * 256 + col] = make_float2(c[2] + bb0, c[3] + bb1);
            }
        }
    }
}

// ---------------------------------------------------------------------------
// u[n][b][o] = pcb[n][o] + sum_i caps[b][n][i] * pcw[n][o][i]
// ---------------------------------------------------------------------------
__global__ void k_caps_u(const float* __restrict__ pcw,
                         const float* __restrict__ pcb) {
    int t = threadIdx.x;
    int b = t >> 3, o = t & 7;
    int n0 = blockIdx.x * 8;
#pragma unroll
    for (int ln = 0; ln < 8; ln++) {
        int n = n0 + ln;
        int g = n / 625, hw = n - g * 625;
        const float4* pw = (const float4*)(pcw + n * 64 + o * 8);
        float4 p0 = __ldg(pw), p1 = __ldg(pw + 1);
        const float4* cp = (const float4*)(g_c3 + (size_t)(b * 625 + hw) * 256 + g * 8);
        float4 c0 = cp[0], c1 = cp[1];
        float u = __ldg(&pcb[n * 8 + o]);
        u += c0.x * p0.x + c0.y * p0.y + c0.z * p0.z + c0.w * p0.w;
        u += c1.x * p1.x + c1.y * p1.y + c1.z * p1.z + c1.w * p1.w;
        g_u[n * 256 + t] = u;
    }
}

// ---------------------------------------------------------------------------
// Fused routing pass, u_hat recomputed on the fly. No smem, no barriers:
// each warp loads its W fragment straight from gmem (L2/L1-resident).
// warp = 4 batches; lane = eh*16+o; e = 2*ep+eh.
// ---------------------------------------------------------------------------
template<int PASS>
__global__ void __launch_bounds__(256) k_pass(const float* __restrict__ W) {
    int tid = threadIdx.x, wid = tid >> 5, lane = tid & 31;
    int eh = lane >> 4, o = lane & 15;
    int b0 = wid * 4;
    int n0 = blockIdx.x * 32;

    float vv0[4][4], vv1[4][4];
    if (PASS >= 1) {
#pragma unroll
        for (int bb = 0; bb < 4; bb++)
#pragma unroll
            for (int ep = 0; ep < 4; ep++) {
                vv0[bb][ep] = g_v0[(b0 + bb) * 128 + ep * 32 + lane];
                if (PASS == 2)
                    vv1[bb][ep] = g_v1[(b0 + bb) * 128 + ep * 32 + lane];
            }
    }

    float accS[4][4];
#pragma unroll
    for (int bb = 0; bb < 4; bb++)
#pragma unroll
        for (int ep = 0; ep < 4; ep++) accS[bb][ep] = 0.f;

    for (int nn = 0; nn < 32; nn++) {
        int n = n0 + nn;
        const float* Wn = W + (size_t)n * 1024;
        float w[4][8];
#pragma unroll
        for (int ep = 0; ep < 4; ep++) {
            const float4* wp = (const float4*)(Wn + (2 * ep + eh) * 128 + o * 8);
            float4 wa = __ldg(wp), wb = __ldg(wp + 1);
            w[ep][0] = wa.x; w[ep][1] = wa.y; w[ep][2] = wa.z; w[ep][3] = wa.w;
            w[ep][4] = wb.x; w[ep][5] = wb.y; w[ep][6] = wb.z; w[ep][7] = wb.w;
        }
        float ureg = __ldg(&g_u[n * 256 + b0 * 8 + lane]);

        float uh[4][4];
#pragma unroll
        for (int bb = 0; bb < 4; bb++)
#pragma unroll
            for (int ep = 0; ep < 4; ep++) uh[bb][ep] = 0.f;

#pragma unroll
        for (int i = 0; i < 8; i++) {
            float ub[4];
#pragma unroll
            for (int bb = 0; bb < 4; bb++)
                ub[bb] = __shfl_sync(0xffffffffu, ureg, bb * 8 + i);
#pragma unroll
            for (int ep = 0; ep < 4; ep++) {
#pragma unroll
                for (int bb = 0; bb < 4; bb++) uh[bb][ep] += ub[bb] * w[ep][i];
            }
        }

        if (PASS == 0) {
#pragma unroll
            for (int bb = 0; bb < 4; bb++)
#pragma unroll
                for (int ep = 0; ep < 4; ep++) accS[bb][ep] += uh[bb][ep];
        } else {
#pragma unroll
            for (int bb = 0; bb < 4; bb++) {
                float a[4], m4 = -1e30f;
#pragma unroll
                for (int ep = 0; ep < 4; ep++) {
                    float p = uh[bb][ep] * vv0[bb][ep];
                    if (PASS == 2) p += uh[bb][ep] * vv1[bb][ep];
#pragma unroll
                    for (int off = 8; off; off >>= 1)
                        p += __shfl_xor_sync(0xffffffffu, p, off);
                    a[ep] = p;
                    m4 = fmaxf(m4, p);
                }
                float amax = fmaxf(m4, __shfl_xor_sync(0xffffffffu, m4, 16));
                float ex[4], s4 = 0.f;
#pragma unroll
                for (int ep = 0; ep < 4; ep++) { ex[ep] = __expf(a[ep] - amax); s4 += ex[ep]; }
                float Z = s4 + __shfl_xor_sync(0xffffffffu, s4, 16);
                float rZ = 1.f / Z;
#pragma unroll
                for (int ep = 0; ep < 4; ep++)
                    accS[bb][ep] += ex[ep] * rZ * uh[bb][ep];
            }
        }
    }

    float* Sout = (PASS == 0) ? g_S0 : (PASS == 1) ? g_S1 : g_S2;
#pragma unroll
    for (int bb = 0; bb < 4; bb++)
#pragma unroll
        for (int ep = 0; ep < 4; ep++)
            atomicAdd(&Sout[(b0 + bb) * 128 + ep * 32 + lane], accS[bb][ep]);
}

// squash S -> v (intermediate iterations)
__global__ void k_squash(int which, float scale) {
    int b = blockIdx.x, t = threadIdx.x;
    const float* S = (which == 0) ? g_S0 : g_S1;
    float* V = (which == 0) ? g_v0 : g_v1;
    float s = S[b * 128 + t] * scale;
    float n2 = s * s;
#pragma unroll
    for (int off = 8; off; off >>= 1)
        n2 += __shfl_xor_sync(0xffffffffu, n2, off);
    float nn = sqrtf(n2);
    V[b * 128 + t] = (n2 / (1.f + n2)) * s / (nn + 1e-8f);
}

// final: ||squash(S2)|| = n2*nn / ((1+n2)*(nn+1e-8)) — no second reduction
__global__ void k_squash_final(float* __restrict__ out) {
    int b = blockIdx.x, t = threadIdx.x;
    float s = g_S2[b * 128 + t];
    float n2 = s * s;
#pragma unroll
    for (int off = 8; off; off >>= 1)
        n2 += __shfl_xor_sync(0xffffffffu, n2, off);
    float nn = sqrtf(n2);
    if ((t & 15) == 0)
        out[b * 8 + (t >> 4)] = n2 * nn / ((1.f + n2) * (nn + 1e-8f));
}

// ===========================================================================
extern "C" void kernel_launch(void* const* d_in, const int* in_sizes, int n_in,
                              void* d_out, int out_size) {
    const float* x   = (const float*)d_in[0];
    const float* w1  = (const float*)d_in[1];
    const float* b1  = (const float*)d_in[2];
    const float* w2  = (const float*)d_in[3];
    const float* b2  = (const float*)d_in[4];
    const float* w3  = (const float*)d_in[5];
    const float* b3  = (const float*)d_in[6];
    const float* pcw = (const float*)d_in[7];
    const float* pcb = (const float*)d_in[8];
    const float* W   = (const float*)d_in[9];
    float* out = (float*)d_out;

    cudaFuncSetAttribute(k_gemm2<0>, cudaFuncAttributeMaxDynamicSharedMemorySize, SMEM_GEMM);
    cudaFuncSetAttribute(k_gemm2<1>, cudaFuncAttributeMaxDynamicSharedMemorySize, SMEM_GEMM);

    k_zero_all<<<14400, 256>>>();
    k_conv1<<<dim3(32, 5), 256>>>(x, w1, b1);
    k_prep_w<<<768, 256>>>(w2, w3);
    k_gemm2<0><<<296, 256, SMEM_GEMM>>>(b2);   // conv2 (profiled slot)
    k_gemm2<1><<<296, 256, SMEM_GEMM>>>(b3);   // conv3
    k_caps_u<<<2500, 256>>>(pcw, pcb);
    k_pass<0><<<625, 256>>>(W);
    k_squash<<<32, 128>>>(0, 0.125f);
    k_pass<1><<<625, 256>>>(W);
    k_squash<<<32, 128>>>(1, 1.f);
    k_pass<2><<<625, 256>>>(W);
    k_squash_final<<<32, 128>>>(out);
}

// round 11
// speedup vs baseline: 1.0254x; 1.0254x over previous
#include <cuda_runtime.h>
#include <cuda_fp16.h>
#include <math.h>
#include <cstdint>

// ===========================================================================
//   conv1 -> conv2 (implicit GEMM M=20000,N=256,K=9216)
//   conv3 (K=512) -> u -> fused routing (on-the-fly u_hat)
//   GEMMs: single-term fp16 mma.sync, fp32 accum, BK=64, 3-stage cp.async.
//   Grid 296: 33xM160 + 115xM128 exact tiles, one wave, SM-paired.
// ===========================================================================

__device__ __align__(16) __half g_xpf[32 * 30 * 30 * 256];   // padded conv1 (fp16)
__device__ __align__(16) __half g_zc[20000 * 512];           // [conv1|conv2] fp16
__device__ __align__(16) __half g_w2f[256 * 9216];
__device__ __align__(16) __half g_w3f[256 * 512];
__device__ float g_c3[20000 * 256];
__device__ float g_u[20000 * 256];       // u[n][b*8+o]
__device__ float g_S0[32 * 128];
__device__ float g_S1[32 * 128];
__device__ float g_S2[32 * 128];

// ---------------------------------------------------------------------------
__global__ void k_zero_all() {
    int i = blockIdx.x * 256 + threadIdx.x;
    if (i < 3686400) ((uint32_t*)g_xpf)[i] = 0u;    // 7372800 halves
    if (i < 32 * 128) { g_S0[i] = 0.f; g_S1[i] = 0.f; g_S2[i] = 0.f; }
}

// conv1: block = (batch, 5 output rows). w1 taps in registers, x tile in smem.
__global__ void __launch_bounds__(256) k_conv1(const float* __restrict__ x,
                                               const float* __restrict__ w1,
                                               const float* __restrict__ b1) {
    __shared__ float xs[14 * 54];
    int b = blockIdx.x;
    int r0 = blockIdx.y * 5;
    int t = threadIdx.x;

    for (int idx = t; idx < 14 * 54; idx += 256) {
        int row = idx / 54, col = idx % 54;
        xs[idx] = x[b * 2916 + (2 * r0 + row) * 54 + col];
    }
    float wr[36];
#pragma unroll
    for (int j = 0; j < 36; j++) wr[j] = __ldg(&w1[t * 36 + j]);
    float bias = __ldg(&b1[t]);
    __syncthreads();

    for (int pr = 0; pr < 5; pr++) {
        int oh = r0 + pr;
#pragma unroll 5
        for (int ow = 0; ow < 25; ow++) {
            float acc = bias;
#pragma unroll
            for (int kh = 0; kh < 6; kh++)
#pragma unroll
                for (int kw = 0; kw < 6; kw++)
                    acc += xs[(2 * pr + kh) * 54 + 2 * ow + kw] * wr[kh * 6 + kw];
            acc = fmaxf(acc, 0.f);
            __half h = __float2half_rn(acc);
            g_xpf[((b * 30 + oh + 2) * 30 + (ow + 2)) * 256 + t] = h;
            g_zc[(b * 625 + oh * 25 + ow) * 512 + t] = h;
        }
    }
}

// fused weight prep: blocks 0..255 -> conv2 w transpose, 256..767 -> conv3 w
__global__ void k_prep_w(const float* __restrict__ w2,
                         const float* __restrict__ w3) {
    __shared__ float s[256 * 37];
    int bx = blockIdx.x;
    int t = threadIdx.x;
    if (bx < 256) {
        int oc = bx;
        for (int j = 0; j < 36; j++) {
            int idx = t + 256 * j;
            int ic = idx / 36, khw = idx % 36;
            s[ic * 37 + khw] = w2[oc * 9216 + idx];
        }
        __syncthreads();
        for (int j = 0; j < 36; j++) {
            int o = t + 256 * j;
            int khw = o >> 8, ic = o & 255;
            g_w2f[oc * 9216 + o] = __float2half_rn(s[ic * 37 + khw]);
        }
    } else {
        int i = (bx - 256) * 256 + t;
        if (i < 131072) g_w3f[i] = __float2half_rn(w3[i]);
    }
}

// ---------------------------------------------------------------------------
// GEMM helpers
// ---------------------------------------------------------------------------
__device__ __forceinline__ uint32_t smem_u32(const void* p) {
    uint32_t a;
    asm("{ .reg .u64 t; cvta.to.shared.u64 t, %1; cvt.u32.u64 %0, t; }" : "=r"(a) : "l"(p));
    return a;
}
__device__ __forceinline__ void cpa16(uint32_t d, const void* g) {
    asm volatile("cp.async.cg.shared.global [%0], [%1], 16;" :: "r"(d), "l"(g) : "memory");
}
#define CP_COMMIT() asm volatile("cp.async.commit_group;" ::: "memory")
#define CP_WAIT(n)  asm volatile("cp.async.wait_group %0;" :: "n"(n) : "memory")

__device__ __forceinline__ void ldsm4(uint32_t& r0, uint32_t& r1, uint32_t& r2, uint32_t& r3,
                                      uint32_t a) {
    asm volatile("ldmatrix.sync.aligned.m8n8.x4.shared.b16 {%0,%1,%2,%3}, [%4];"
                 : "=r"(r0), "=r"(r1), "=r"(r2), "=r"(r3) : "r"(a));
}
__device__ __forceinline__ void mma16816(float& c0, float& c1, float& c2, float& c3,
                                         uint32_t a0, uint32_t a1, uint32_t a2, uint32_t a3,
                                         uint32_t b0, uint32_t b1) {
    asm volatile("mma.sync.aligned.m16n8k16.row.col.f32.f16.f16.f32 "
                 "{%0,%1,%2,%3}, {%4,%5,%6,%7}, {%8,%9}, {%0,%1,%2,%3};"
                 : "+f"(c0), "+f"(c1), "+f"(c2), "+f"(c3)
                 : "r"(a0), "r"(a1), "r"(a2), "r"(a3), "r"(b0), "r"(b1));
}

// 128B rows, 8x16B chunks, chunk ^= row&7 -> conflict-free cp.async + ldmatrix
__device__ __forceinline__ uint32_t swad(uint32_t region, int row, int chunk) {
    return region + (uint32_t)row * 128u + (uint32_t)((chunk ^ (row & 7)) << 4);
}

// stage: A up to 160x64 fp16 (20480B) | B 128x64 (16384B)
#define OFF_B  20480
#define STGSZ  36864
#define SMEM_GEMM (3 * STGSZ)

// Tile map (exact cover, bids i and i+148 share an SM):
//  slot<66 & wave0 -> M160 tile, else M128.
template<int MODE>
__global__ void __launch_bounds__(256, 2) k_gemm2(const float* __restrict__ bias) {
    constexpr int K = (MODE == 0) ? 9216 : 512;
    constexpr int S = K / 64;
    extern __shared__ char sm[];
    __shared__ int s_rowbase[160];
    const uint32_t sbase = smem_u32(sm);
    const int tid = threadIdx.x;

    int sslot = blockIdx.x % 148, wave = blockIdx.x / 148;
    int MI, m0, n0;
    if (sslot < 66 && wave == 0) {
        MI = 5; m0 = (sslot >> 1) * 160; n0 = (sslot & 1) * 128;
    } else {
        int j = (wave == 0) ? (sslot - 66) : (82 + sslot);
        MI = 4; m0 = 5280 + (j >> 1) * 128; n0 = (j & 1) * 128;
    }
    const int achunks = MI * 256;          // A rows(MI*32) * 8 chunks

    if (MODE == 0 && tid < 160) {
        int m = min(m0 + tid, 19999);
        int b = m / 625, p = m % 625, oh = p / 25, ow = p % 25;
        s_rowbase[tid] = ((b * 30 + oh) * 30 + ow) * 256;
    }
    __syncthreads();

    const __half* WH = (MODE == 0) ? g_w2f : g_w3f;

    auto issue = [&](int s) {
        int k0 = s * 64;
        uint32_t dbase = sbase + (s % 3) * STGSZ;
        int aoff = 0;
        if (MODE == 0) {
            int khw = k0 >> 8;
            int kh = khw / 6, kw = khw - kh * 6;
            aoff = (kh * 30 + kw) * 256 + (k0 & 255);
        }
#pragma unroll
        for (int j = 0; j < 9; j++) {
            int c = tid + j * 256;
            if (c < achunks) {                   // A region
                int row = c >> 3, kc = c & 7;
                const __half* src;
                if (MODE == 0) src = g_xpf + s_rowbase[row] + aoff + kc * 8;
                else           src = g_zc + (size_t)(m0 + row) * 512 + k0 + kc * 8;
                cpa16(swad(dbase, row, kc), src);
            } else if (c < achunks + 1024) {     // B
                int c2 = c - achunks;
                int row = c2 >> 3, kc = c2 & 7;
                cpa16(swad(dbase + OFF_B, row, kc),
                      WH + (size_t)(n0 + row) * K + k0 + kc * 8);
            }
        }
        CP_COMMIT();
    };

    const int lane = tid & 31, wid = tid >> 5;
    const int wm = (wid & 1) * (MI * 16), wn = (wid >> 1) * 32;
    const int grp = lane >> 2, q = lane & 3;
    const int lrow = lane & 15, lk = lane >> 4;

    float acc[5][4][4];
#pragma unroll
    for (int i = 0; i < 5; i++)
#pragma unroll
        for (int j = 0; j < 4; j++)
#pragma unroll
            for (int c = 0; c < 4; c++) acc[i][j][c] = 0.f;

    issue(0);
    issue(1);

    for (int s = 0; s < S; s++) {
        if (s < S - 1) CP_WAIT(1); else CP_WAIT(0);
        __syncthreads();
        if (s + 2 < S) issue(s + 2);

        uint32_t Ar = sbase + (s % 3) * STGSZ;
        uint32_t Br = Ar + OFF_B;

#pragma unroll
        for (int kk = 0; kk < 4; kk++) {
            int ckc = kk * 2 + lk;               // 0..7
            uint32_t bh[4][2];
#pragma unroll
            for (int p2 = 0; p2 < 2; p2++) {
                int row = wn + p2 * 16 + lrow;
                uint32_t r0, r1, r2, r3;
                ldsm4(r0, r1, r2, r3, swad(Br, row, ckc));
                bh[2 * p2][0] = r0; bh[2 * p2][1] = r2;
                bh[2 * p2 + 1][0] = r1; bh[2 * p2 + 1][1] = r3;
            }
#pragma unroll
            for (int mi = 0; mi < 4; mi++) {
                uint32_t a0, a1, a2, a3;
                ldsm4(a0, a1, a2, a3, swad(Ar, wm + mi * 16 + lrow, ckc));
#pragma unroll
                for (int ni = 0; ni < 4; ni++) {
                    float* c = acc[mi][ni];
                    mma16816(c[0], c[1], c[2], c[3], a0, a1, a2, a3,
                             bh[ni][0], bh[ni][1]);
                }
            }
            if (MI == 5) {
                uint32_t a0, a1, a2, a3;
                ldsm4(a0, a1, a2, a3, swad(Ar, wm + 64 + lrow, ckc));
#pragma unroll
                for (int ni = 0; ni < 4; ni++) {
                    float* c = acc[4][ni];
                    mma16816(c[0], c[1], c[2], c[3], a0, a1, a2, a3,
                             bh[ni][0], bh[ni][1]);
                }
            }
        }
    }
    __syncthreads();

    // epilogue (exact tiles, every row written once)
#pragma unroll
    for (int mi = 0; mi < 5; mi++) {
        if (mi == 4 && MI != 5) break;
#pragma unroll
        for (int ni = 0; ni < 4; ni++) {
            int col = n0 + wn + ni * 8 + 2 * q;
            float bb0 = bias[col], bb1 = bias[col + 1];
            int row0 = m0 + wm + mi * 16 + grp;
            int row1 = row0 + 8;
            float* c = acc[mi][ni];
            if (MODE == 0) {
                float v0 = fmaxf(c[0] + bb0, 0.f), v1 = fmaxf(c[1] + bb1, 0.f);
                __half2 h01; h01.x = __float2half_rn(v0); h01.y = __float2half_rn(v1);
                *(__half2*)&g_zc[(size_t)row0 * 512 + 256 + col] = h01;
                float v2 = fmaxf(c[2] + bb0, 0.f), v3 = fmaxf(c[3] + bb1, 0.f);
                __half2 h23; h23.x = __float2half_rn(v2); h23.y = __float2half_rn(v3);
                *(__half2*)&g_zc[(size_t)row1 * 512 + 256 + col] = h23;
            } else {
                *(float2*)&g_c3[(size_t)row0 * 256 + col] = make_float2(c[0] + bb0, c[1] + bb1);
                *(float2*)&g_c3[(size_t)row1 * 256 + col] = make_float2(c[2] + bb0, c[3] + bb1);
            }
        }
    }
}

// ---------------------------------------------------------------------------
// u[n][b][o] = pcb[n][o] + sum_i caps[b][n][i] * pcw[n][o][i]
// ---------------------------------------------------------------------------
__global__ void k_caps_u(const float* __restrict__ pcw,
                         const float* __restrict__ pcb) {
    int t = threadIdx.x;
    int b = t >> 3, o = t & 7;
    int n0 = blockIdx.x * 8;
#pragma unroll
    for (int ln = 0; ln < 8; ln++) {
        int n = n0 + ln;
        int g = n / 625, hw = n - g * 625;
        const float4* pw = (const float4*)(pcw + n * 64 + o * 8);
        float4 p0 = __ldg(pw), p1 = __ldg(pw + 1);
        const float4* cp = (const float4*)(g_c3 + (size_t)(b * 625 + hw) * 256 + g * 8);
        float4 c0 = cp[0], c1 = cp[1];
        float u = __ldg(&pcb[n * 8 + o]);
        u += c0.x * p0.x + c0.y * p0.y + c0.z * p0.z + c0.w * p0.w;
        u += c1.x * p1.x + c1.y * p1.y + c1.z * p1.z + c1.w * p1.w;
        g_u[n * 256 + t] = u;
    }
}

// ---------------------------------------------------------------------------
// Fused routing pass, u_hat recomputed on the fly; W staged in smem;
// v0/v1 squashed inline from S0/S1 (no separate squash kernels).
// warp = 4 batches; lane = eh*16+o; e = 2*ep+eh.
// ---------------------------------------------------------------------------
template<int PASS>
__global__ void __launch_bounds__(256) k_pass(const float* __restrict__ W) {
    __shared__ float sW[8 * 128];
    int tid = threadIdx.x, wid = tid >> 5, lane = tid & 31;
    int b0 = wid * 4;
    int n0 = blockIdx.x * 32;

    float vv0[4][4], vv1[4][4];
    if (PASS >= 1) {
#pragma unroll
        for (int bb = 0; bb < 4; bb++)
#pragma unroll
            for (int ep = 0; ep < 4; ep++) {
                int idx = (b0 + bb) * 128 + ep * 32 + lane;
                {   // v0 = squash(S0 / 8)
                    float s = g_S0[idx] * 0.125f;
                    float n2 = s * s;
#pragma unroll
                    for (int off = 8; off; off >>= 1)
                        n2 += __shfl_xor_sync(0xffffffffu, n2, off);
                    float nn = sqrtf(n2);
                    vv0[bb][ep] = (n2 / (1.f + n2)) * s / (nn + 1e-8f);
                }
                if (PASS == 2) {   // v1 = squash(S1)
                    float s = g_S1[idx];
                    float n2 = s * s;
#pragma unroll
                    for (int off = 8; off; off >>= 1)
                        n2 += __shfl_xor_sync(0xffffffffu, n2, off);
                    float nn = sqrtf(n2);
                    vv1[bb][ep] = (n2 / (1.f + n2)) * s / (nn + 1e-8f);
                }
            }
    }

    float accS[4][4];
#pragma unroll
    for (int bb = 0; bb < 4; bb++)
#pragma unroll
        for (int ep = 0; ep < 4; ep++) accS[bb][ep] = 0.f;

    for (int nn = 0; nn < 32; nn++) {
        int n = n0 + nn;
        __syncthreads();
        {
            float4 wv = *(const float4*)&W[(size_t)n * 1024 + tid * 4];
            int eo = tid >> 1, i0 = (tid & 1) * 4;
            sW[(i0 + 0) * 128 + eo] = wv.x;
            sW[(i0 + 1) * 128 + eo] = wv.y;
            sW[(i0 + 2) * 128 + eo] = wv.z;
            sW[(i0 + 3) * 128 + eo] = wv.w;
        }
        __syncthreads();

        float ureg = g_u[n * 256 + b0 * 8 + lane];

        float uh[4][4];
#pragma unroll
        for (int bb = 0; bb < 4; bb++)
#pragma unroll
            for (int ep = 0; ep < 4; ep++) uh[bb][ep] = 0.f;

#pragma unroll
        for (int i = 0; i < 8; i++) {
            float ub[4];
#pragma unroll
            for (int bb = 0; bb < 4; bb++)
                ub[bb] = __shfl_sync(0xffffffffu, ureg, bb * 8 + i);
#pragma unroll
            for (int ep = 0; ep < 4; ep++) {
                float w = sW[i * 128 + ep * 32 + lane];
#pragma unroll
                for (int bb = 0; bb < 4; bb++) uh[bb][ep] += ub[bb] * w;
            }
        }

        if (PASS == 0) {
#pragma unroll
            for (int bb = 0; bb < 4; bb++)
#pragma unroll
                for (int ep = 0; ep < 4; ep++) accS[bb][ep] += uh[bb][ep];
        } else {
#pragma unroll
            for (int bb = 0; bb < 4; bb++) {
                float a[4], m4 = -1e30f;
#pragma unroll
                for (int ep = 0; ep < 4; ep++) {
                    float p = uh[bb][ep] * vv0[bb][ep];
                    if (PASS == 2) p += uh[bb][ep] * vv1[bb][ep];
#pragma unroll
                    for (int off = 8; off; off >>= 1)
                        p += __shfl_xor_sync(0xffffffffu, p, off);
                    a[ep] = p;
                    m4 = fmaxf(m4, p);
                }
                float amax = fmaxf(m4, __shfl_xor_sync(0xffffffffu, m4, 16));
                float ex[4], s4 = 0.f;
#pragma unroll
                for (int ep = 0; ep < 4; ep++) { ex[ep] = __expf(a[ep] - amax); s4 += ex[ep]; }
                float Z = s4 + __shfl_xor_sync(0xffffffffu, s4, 16);
                float rZ = 1.f / Z;
#pragma unroll
                for (int ep = 0; ep < 4; ep++)
                    accS[bb][ep] += ex[ep] * rZ * uh[bb][ep];
            }
        }
    }

    float* Sout = (PASS == 0) ? g_S0 : (PASS == 1) ? g_S1 : g_S2;
#pragma unroll
    for (int bb = 0; bb < 4; bb++)
#pragma unroll
        for (int ep = 0; ep < 4; ep++)
            atomicAdd(&Sout[(b0 + bb) * 128 + ep * 32 + lane], accS[bb][ep]);
}

// final: ||squash(S2)|| = n2*nn / ((1+n2)*(nn+1e-8)) — single reduction
__global__ void k_squash_final(float* __restrict__ out) {
    int b = blockIdx.x, t = threadIdx.x;
    float s = g_S2[b * 128 + t];
    float n2 = s * s;
#pragma unroll
    for (int off = 8; off; off >>= 1)
        n2 += __shfl_xor_sync(0xffffffffu, n2, off);
    float nn = sqrtf(n2);
    if ((t & 15) == 0)
        out[b * 8 + (t >> 4)] = n2 * nn / ((1.f + n2) * (nn + 1e-8f));
}

// ===========================================================================
extern "C" void kernel_launch(void* const* d_in, const int* in_sizes, int n_in,
                              void* d_out, int out_size) {
    const float* x   = (const float*)d_in[0];
    const float* w1  = (const float*)d_in[1];
    const float* b1  = (const float*)d_in[2];
    const float* w2  = (const float*)d_in[3];
    const float* b2  = (const float*)d_in[4];
    const float* w3  = (const float*)d_in[5];
    const float* b3  = (const float*)d_in[6];
    const float* pcw = (const float*)d_in[7];
    const float* pcb = (const float*)d_in[8];
    const float* W   = (const float*)d_in[9];
    float* out = (float*)d_out;

    cudaFuncSetAttribute(k_gemm2<0>, cudaFuncAttributeMaxDynamicSharedMemorySize, SMEM_GEMM);
    cudaFuncSetAttribute(k_gemm2<1>, cudaFuncAttributeMaxDynamicSharedMemorySize, SMEM_GEMM);

    k_zero_all<<<14400, 256>>>();
    k_conv1<<<dim3(32, 5), 256>>>(x, w1, b1);
    k_prep_w<<<768, 256>>>(w2, w3);
    k_gemm2<0><<<296, 256, SMEM_GEMM>>>(b2);   // conv2 (profiled slot)
    k_gemm2<1><<<296, 256, SMEM_GEMM>>>(b3);   // conv3
    k_caps_u<<<2500, 256>>>(pcw, pcb);
    k_pass<0><<<625, 256>>>(W);
    k_pass<1><<<625, 256>>>(W);
    k_pass<2><<<625, 256>>>(W);
    k_squash_final<<<32, 128>>>(out);
}

// round 12
// speedup vs baseline: 1.0444x; 1.0185x over previous
#include <cuda_runtime.h>
#include <cuda_fp16.h>
#include <math.h>
#include <cstdint>

// ===========================================================================
//   conv1 -> conv2 (implicit GEMM M=20000,N=256,K=9216)
//   conv3 (K=512) -> u -> fused routing (on-the-fly u_hat, thread-local o)
//   GEMMs: single-term fp16 mma.sync, fp32 accum, BK=64, 3-stage cp.async.
//   Grid 296: 33xM160 + 115xM128 exact tiles, one wave, SM-paired.
// ===========================================================================

__device__ __align__(16) __half g_xpf[32 * 30 * 30 * 256];   // padded conv1 (fp16)
__device__ __align__(16) __half g_zc[20000 * 512];           // [conv1|conv2] fp16
__device__ __align__(16) __half g_w2f[256 * 9216];
__device__ __align__(16) __half g_w3f[256 * 512];
__device__ float g_c3[20000 * 256];
__device__ float g_u[20000 * 256];       // u[n][b*8+i]
__device__ float g_S0[32 * 128];
__device__ float g_S1[32 * 128];
__device__ float g_S2[32 * 128];

// ---------------------------------------------------------------------------
__global__ void k_zero_all() {
    int i = blockIdx.x * 256 + threadIdx.x;
    if (i < 3686400) ((uint32_t*)g_xpf)[i] = 0u;    // 7372800 halves
    if (i < 32 * 128) { g_S0[i] = 0.f; g_S1[i] = 0.f; g_S2[i] = 0.f; }
}

// conv1: block = (batch, 5 output rows). w1 taps in registers, x tile in smem.
__global__ void __launch_bounds__(256) k_conv1(const float* __restrict__ x,
                                               const float* __restrict__ w1,
                                               const float* __restrict__ b1) {
    __shared__ float xs[14 * 54];
    int b = blockIdx.x;
    int r0 = blockIdx.y * 5;
    int t = threadIdx.x;

    for (int idx = t; idx < 14 * 54; idx += 256) {
        int row = idx / 54, col = idx % 54;
        xs[idx] = x[b * 2916 + (2 * r0 + row) * 54 + col];
    }
    float wr[36];
#pragma unroll
    for (int j = 0; j < 36; j++) wr[j] = __ldg(&w1[t * 36 + j]);
    float bias = __ldg(&b1[t]);
    __syncthreads();

    for (int pr = 0; pr < 5; pr++) {
        int oh = r0 + pr;
#pragma unroll 5
        for (int ow = 0; ow < 25; ow++) {
            float acc = bias;
#pragma unroll
            for (int kh = 0; kh < 6; kh++)
#pragma unroll
                for (int kw = 0; kw < 6; kw++)
                    acc += xs[(2 * pr + kh) * 54 + 2 * ow + kw] * wr[kh * 6 + kw];
            acc = fmaxf(acc, 0.f);
            __half h = __float2half_rn(acc);
            g_xpf[((b * 30 + oh + 2) * 30 + (ow + 2)) * 256 + t] = h;
            g_zc[(b * 625 + oh * 25 + ow) * 512 + t] = h;
        }
    }
}

// fused weight prep: blocks 0..255 -> conv2 w transpose, 256..767 -> conv3 w
__global__ void k_prep_w(const float* __restrict__ w2,
                         const float* __restrict__ w3) {
    __shared__ float s[256 * 37];
    int bx = blockIdx.x;
    int t = threadIdx.x;
    if (bx < 256) {
        int oc = bx;
        for (int j = 0; j < 36; j++) {
            int idx = t + 256 * j;
            int ic = idx / 36, khw = idx % 36;
            s[ic * 37 + khw] = w2[oc * 9216 + idx];
        }
        __syncthreads();
        for (int j = 0; j < 36; j++) {
            int o = t + 256 * j;
            int khw = o >> 8, ic = o & 255;
            g_w2f[oc * 9216 + o] = __float2half_rn(s[ic * 37 + khw]);
        }
    } else {
        int i = (bx - 256) * 256 + t;
        if (i < 131072) g_w3f[i] = __float2half_rn(w3[i]);
    }
}

// ---------------------------------------------------------------------------
// GEMM helpers
// ---------------------------------------------------------------------------
__device__ __forceinline__ uint32_t smem_u32(const void* p) {
    uint32_t a;
    asm("{ .reg .u64 t; cvta.to.shared.u64 t, %1; cvt.u32.u64 %0, t; }" : "=r"(a) : "l"(p));
    return a;
}
__device__ __forceinline__ void cpa16(uint32_t d, const void* g) {
    asm volatile("cp.async.cg.shared.global [%0], [%1], 16;" :: "r"(d), "l"(g) : "memory");
}
#define CP_COMMIT() asm volatile("cp.async.commit_group;" ::: "memory")
#define CP_WAIT(n)  asm volatile("cp.async.wait_group %0;" :: "n"(n) : "memory")

__device__ __forceinline__ void ldsm4(uint32_t& r0, uint32_t& r1, uint32_t& r2, uint32_t& r3,
                                      uint32_t a) {
    asm volatile("ldmatrix.sync.aligned.m8n8.x4.shared.b16 {%0,%1,%2,%3}, [%4];"
                 : "=r"(r0), "=r"(r1), "=r"(r2), "=r"(r3) : "r"(a));
}
__device__ __forceinline__ void mma16816(float& c0, float& c1, float& c2, float& c3,
                                         uint32_t a0, uint32_t a1, uint32_t a2, uint32_t a3,
                                         uint32_t b0, uint32_t b1) {
    asm volatile("mma.sync.aligned.m16n8k16.row.col.f32.f16.f16.f32 "
                 "{%0,%1,%2,%3}, {%4,%5,%6,%7}, {%8,%9}, {%0,%1,%2,%3};"
                 : "+f"(c0), "+f"(c1), "+f"(c2), "+f"(c3)
                 : "r"(a0), "r"(a1), "r"(a2), "r"(a3), "r"(b0), "r"(b1));
}

// 128B rows, 8x16B chunks, chunk ^= row&7 -> conflict-free cp.async + ldmatrix
__device__ __forceinline__ uint32_t swad(uint32_t region, int row, int chunk) {
    return region + (uint32_t)row * 128u + (uint32_t)((chunk ^ (row & 7)) << 4);
}

// stage: A up to 160x64 fp16 (20480B) | B 128x64 (16384B)
#define OFF_B  20480
#define STGSZ  36864
#define SMEM_GEMM (3 * STGSZ)

template<int MODE>
__global__ void __launch_bounds__(256, 2) k_gemm2(const float* __restrict__ bias) {
    constexpr int K = (MODE == 0) ? 9216 : 512;
    constexpr int S = K / 64;
    extern __shared__ char sm[];
    __shared__ int s_rowbase[160];
    const uint32_t sbase = smem_u32(sm);
    const int tid = threadIdx.x;

    int sslot = blockIdx.x % 148, wave = blockIdx.x / 148;
    int MI, m0, n0;
    if (sslot < 66 && wave == 0) {
        MI = 5; m0 = (sslot >> 1) * 160; n0 = (sslot & 1) * 128;
    } else {
        int j = (wave == 0) ? (sslot - 66) : (82 + sslot);
        MI = 4; m0 = 5280 + (j >> 1) * 128; n0 = (j & 1) * 128;
    }
    const int achunks = MI * 256;          // A rows(MI*32) * 8 chunks

    if (MODE == 0 && tid < 160) {
        int m = min(m0 + tid, 19999);
        int b = m / 625, p = m % 625, oh = p / 25, ow = p % 25;
        s_rowbase[tid] = ((b * 30 + oh) * 30 + ow) * 256;
    }
    __syncthreads();

    const __half* WH = (MODE == 0) ? g_w2f : g_w3f;

    auto issue = [&](int s) {
        int k0 = s * 64;
        uint32_t dbase = sbase + (s % 3) * STGSZ;
        int aoff = 0;
        if (MODE == 0) {
            int khw = k0 >> 8;
            int kh = khw / 6, kw = khw - kh * 6;
            aoff = (kh * 30 + kw) * 256 + (k0 & 255);
        }
#pragma unroll
        for (int j = 0; j < 9; j++) {
            int c = tid + j * 256;
            if (c < achunks) {                   // A region
                int row = c >> 3, kc = c & 7;
                const __half* src;
                if (MODE == 0) src = g_xpf + s_rowbase[row] + aoff + kc * 8;
                else           src = g_zc + (size_t)(m0 + row) * 512 + k0 + kc * 8;
                cpa16(swad(dbase, row, kc), src);
            } else if (c < achunks + 1024) {     // B
                int c2 = c - achunks;
                int row = c2 >> 3, kc = c2 & 7;
                cpa16(swad(dbase + OFF_B, row, kc),
                      WH + (size_t)(n0 + row) * K + k0 + kc * 8);
            }
        }
        CP_COMMIT();
    };

    const int lane = tid & 31, wid = tid >> 5;
    const int wm = (wid & 1) * (MI * 16), wn = (wid >> 1) * 32;
    const int grp = lane >> 2, q = lane & 3;
    const int lrow = lane & 15, lk = lane >> 4;

    float acc[5][4][4];
#pragma unroll
    for (int i = 0; i < 5; i++)
#pragma unroll
        for (int j = 0; j < 4; j++)
#pragma unroll
            for (int c = 0; c < 4; c++) acc[i][j][c] = 0.f;

    issue(0);
    issue(1);

    for (int s = 0; s < S; s++) {
        if (s < S - 1) CP_WAIT(1); else CP_WAIT(0);
        __syncthreads();
        if (s + 2 < S) issue(s + 2);

        uint32_t Ar = sbase + (s % 3) * STGSZ;
        uint32_t Br = Ar + OFF_B;

#pragma unroll
        for (int kk = 0; kk < 4; kk++) {
            int ckc = kk * 2 + lk;
            uint32_t bh[4][2];
#pragma unroll
            for (int p2 = 0; p2 < 2; p2++) {
                int row = wn + p2 * 16 + lrow;
                uint32_t r0, r1, r2, r3;
                ldsm4(r0, r1, r2, r3, swad(Br, row, ckc));
                bh[2 * p2][0] = r0; bh[2 * p2][1] = r2;
                bh[2 * p2 + 1][0] = r1; bh[2 * p2 + 1][1] = r3;
            }
#pragma unroll
            for (int mi = 0; mi < 4; mi++) {
                uint32_t a0, a1, a2, a3;
                ldsm4(a0, a1, a2, a3, swad(Ar, wm + mi * 16 + lrow, ckc));
#pragma unroll
                for (int ni = 0; ni < 4; ni++) {
                    float* c = acc[mi][ni];
                    mma16816(c[0], c[1], c[2], c[3], a0, a1, a2, a3,
                             bh[ni][0], bh[ni][1]);
                }
            }
            if (MI == 5) {
                uint32_t a0, a1, a2, a3;
                ldsm4(a0, a1, a2, a3, swad(Ar, wm + 64 + lrow, ckc));
#pragma unroll
                for (int ni = 0; ni < 4; ni++) {
                    float* c = acc[4][ni];
                    mma16816(c[0], c[1], c[2], c[3], a0, a1, a2, a3,
                             bh[ni][0], bh[ni][1]);
                }
            }
        }
    }
    __syncthreads();

    // epilogue (exact tiles, every row written once)
#pragma unroll
    for (int mi = 0; mi < 5; mi++) {
        if (mi == 4 && MI != 5) break;
#pragma unroll
        for (int ni = 0; ni < 4; ni++) {
            int col = n0 + wn + ni * 8 + 2 * q;
            float bb0 = bias[col], bb1 = bias[col + 1];
            int row0 = m0 + wm + mi * 16 + grp;
            int row1 = row0 + 8;
            float* c = acc[mi][ni];
            if (MODE == 0) {
                float v0 = fmaxf(c[0] + bb0, 0.f), v1 = fmaxf(c[1] + bb1, 0.f);
                __half2 h01; h01.x = __float2half_rn(v0); h01.y = __float2half_rn(v1);
                *(__half2*)&g_zc[(size_t)row0 * 512 + 256 + col] = h01;
                float v2 = fmaxf(c[2] + bb0, 0.f), v3 = fmaxf(c[3] + bb1, 0.f);
                __half2 h23; h23.x = __float2half_rn(v2); h23.y = __float2half_rn(v3);
                *(__half2*)&g_zc[(size_t)row1 * 512 + 256 + col] = h23;
            } else {
                *(float2*)&g_c3[(size_t)row0 * 256 + col] = make_float2(c[0] + bb0, c[1] + bb1);
                *(float2*)&g_c3[(size_t)row1 * 256 + col] = make_float2(c[2] + bb0, c[3] + bb1);
            }
        }
    }
}

// ---------------------------------------------------------------------------
// u[n][b][i] = pcb[n][i] + sum_j caps[b][n][j] * pcw[n][i][j]
// ---------------------------------------------------------------------------
__global__ void k_caps_u(const float* __restrict__ pcw,
                         const float* __restrict__ pcb) {
    int t = threadIdx.x;
    int b = t >> 3, o = t & 7;
    int n0 = blockIdx.x * 8;
#pragma unroll
    for (int ln = 0; ln < 8; ln++) {
        int n = n0 + ln;
        int g = n / 625, hw = n - g * 625;
        const float4* pw = (const float4*)(pcw + n * 64 + o * 8);
        float4 p0 = __ldg(pw), p1 = __ldg(pw + 1);
        const float4* cp = (const float4*)(g_c3 + (size_t)(b * 625 + hw) * 256 + g * 8);
        float4 c0 = cp[0], c1 = cp[1];
        float u = __ldg(&pcb[n * 8 + o]);
        u += c0.x * p0.x + c0.y * p0.y + c0.z * p0.z + c0.w * p0.w;
        u += c1.x * p1.x + c1.y * p1.y + c1.z * p1.z + c1.w * p1.w;
        g_u[n * 256 + t] = u;
    }
}

// ---------------------------------------------------------------------------
// Fused routing pass. Thread owns (b, e) with ALL 16 o in registers:
//   - uh, dot, squash(v), c*uh accumulation all thread-local
//   - softmax over e = 6 shfl_xor within 8-lane groups
//   - W staged in smem 4 n at a time (e-stride padded to 132 floats)
//   - u tile (32 n x 256) staged once per block
// warp w -> batches w*4 + lane/8 ; e = lane%8.
// ---------------------------------------------------------------------------
template<int PASS>
__global__ void __launch_bounds__(256) k_pass(const float* __restrict__ W) {
    __shared__ float sU[32][256];       // 32 KB
    __shared__ float sW[4][1056];       // 16.9 KB (8 e x 132)
    int t = threadIdx.x, wid = t >> 5, lane = t & 31;
    int b = wid * 4 + (lane >> 3);
    int e = lane & 7;
    int n0 = blockIdx.x * 32;

    // stage u tile (coalesced)
#pragma unroll
    for (int j = 0; j < 8; j++) {
        int idx = t + j * 256;          // float4 slot: 2048 total
        int nn = idx >> 6, pos = idx & 63;
        ((float4*)sU[nn])[pos] = __ldg((const float4*)&g_u[(size_t)(n0 + nn) * 256] + pos);
    }

    // thread-local v0/v1 (squash over o is thread-local!)
    float vv0[16], vv1[16];
    if (PASS >= 1) {
        float sv[16], n2 = 0.f;
#pragma unroll
        for (int o4 = 0; o4 < 4; o4++) {
            float4 s4 = __ldg((const float4*)&g_S0[b * 128 + e * 16 + o4 * 4]);
            sv[o4 * 4 + 0] = s4.x * 0.125f; sv[o4 * 4 + 1] = s4.y * 0.125f;
            sv[o4 * 4 + 2] = s4.z * 0.125f; sv[o4 * 4 + 3] = s4.w * 0.125f;
        }
#pragma unroll
        for (int o = 0; o < 16; o++) n2 += sv[o] * sv[o];
        float nn = sqrtf(n2);
        float f = (n2 / (1.f + n2)) / (nn + 1e-8f);
#pragma unroll
        for (int o = 0; o < 16; o++) vv0[o] = sv[o] * f;
        if (PASS == 2) {
            float n2b = 0.f;
#pragma unroll
            for (int o4 = 0; o4 < 4; o4++) {
                float4 s4 = __ldg((const float4*)&g_S1[b * 128 + e * 16 + o4 * 4]);
                sv[o4 * 4 + 0] = s4.x; sv[o4 * 4 + 1] = s4.y;
                sv[o4 * 4 + 2] = s4.z; sv[o4 * 4 + 3] = s4.w;
            }
#pragma unroll
            for (int o = 0; o < 16; o++) n2b += sv[o] * sv[o];
            float nnb = sqrtf(n2b);
            float fb = (n2b / (1.f + n2b)) / (nnb + 1e-8f);
#pragma unroll
            for (int o = 0; o < 16; o++) vv1[o] = sv[o] * fb;
        }
    }

    float accS[16];
#pragma unroll
    for (int o = 0; o < 16; o++) accS[o] = 0.f;

    // W stage dest mapping for this thread
    int we = t >> 5, wrem = t & 31;
    int wo = wrem >> 1, wi0 = (wrem & 1) * 4;
    int wdst = we * 132 + wo * 8 + wi0;

    __syncthreads();

    for (int g = 0; g < 8; g++) {
        if (g) __syncthreads();
#pragma unroll
        for (int j = 0; j < 4; j++) {
            float4 wv = __ldg((const float4*)&W[(size_t)(n0 + g * 4 + j) * 1024] + t);
            *(float4*)&sW[j][wdst] = wv;
        }
        __syncthreads();

#pragma unroll
        for (int j = 0; j < 4; j++) {
            int nl = g * 4 + j;
            float4 ua = *(float4*)&sU[nl][b * 8];
            float4 ub = *(float4*)&sU[nl][b * 8 + 4];
            float uh[16];
#pragma unroll
            for (int o = 0; o < 16; o++) {
                float4 wa = *(float4*)&sW[j][e * 132 + o * 8];
                float4 wb = *(float4*)&sW[j][e * 132 + o * 8 + 4];
                uh[o] = ua.x * wa.x + ua.y * wa.y + ua.z * wa.z + ua.w * wa.w
                      + ub.x * wb.x + ub.y * wb.y + ub.z * wb.z + ub.w * wb.w;
            }
            if (PASS == 0) {
#pragma unroll
                for (int o = 0; o < 16; o++) accS[o] += uh[o];
            } else {
                float d = 0.f;
#pragma unroll
                for (int o = 0; o < 16; o++) d += uh[o] * vv0[o];
                if (PASS == 2) {
#pragma unroll
                    for (int o = 0; o < 16; o++) d += uh[o] * vv1[o];
                }
                float m = d;
                m = fmaxf(m, __shfl_xor_sync(0xffffffffu, m, 1));
                m = fmaxf(m, __shfl_xor_sync(0xffffffffu, m, 2));
                m = fmaxf(m, __shfl_xor_sync(0xffffffffu, m, 4));
                float ex = __expf(d - m);
                float Z = ex;
                Z += __shfl_xor_sync(0xffffffffu, Z, 1);
                Z += __shfl_xor_sync(0xffffffffu, Z, 2);
                Z += __shfl_xor_sync(0xffffffffu, Z, 4);
                float c = ex / Z;
#pragma unroll
                for (int o = 0; o < 16; o++) accS[o] += c * uh[o];
            }
        }
    }

    float* Sout = (PASS == 0) ? g_S0 : (PASS == 1) ? g_S1 : g_S2;
#pragma unroll
    for (int o = 0; o < 16; o++)
        atomicAdd(&Sout[b * 128 + e * 16 + o], accS[o]);
}

// final: ||squash(S2)|| = n2*nn / ((1+n2)*(nn+1e-8)) — single reduction
__global__ void k_squash_final(float* __restrict__ out) {
    int b = blockIdx.x, t = threadIdx.x;
    float s = g_S2[b * 128 + t];
    float n2 = s * s;
#pragma unroll
    for (int off = 8; off; off >>= 1)
        n2 += __shfl_xor_sync(0xffffffffu, n2, off);
    float nn = sqrtf(n2);
    if ((t & 15) == 0)
        out[b * 8 + (t >> 4)] = n2 * nn / ((1.f + n2) * (nn + 1e-8f));
}

// ===========================================================================
extern "C" void kernel_launch(void* const* d_in, const int* in_sizes, int n_in,
                              void* d_out, int out_size) {
    const float* x   = (const float*)d_in[0];
    const float* w1  = (const float*)d_in[1];
    const float* b1  = (const float*)d_in[2];
    const float* w2  = (const float*)d_in[3];
    const float* b2  = (const float*)d_in[4];
    const float* w3  = (const float*)d_in[5];
    const float* b3  = (const float*)d_in[6];
    const float* pcw = (const float*)d_in[7];
    const float* pcb = (const float*)d_in[8];
    const float* W   = (const float*)d_in[9];
    float* out = (float*)d_out;

    cudaFuncSetAttribute(k_gemm2<0>, cudaFuncAttributeMaxDynamicSharedMemorySize, SMEM_GEMM);
    cudaFuncSetAttribute(k_gemm2<1>, cudaFuncAttributeMaxDynamicSharedMemorySize, SMEM_GEMM);

    k_zero_all<<<14400, 256>>>();
    k_conv1<<<dim3(32, 5), 256>>>(x, w1, b1);
    k_prep_w<<<768, 256>>>(w2, w3);
    k_gemm2<0><<<296, 256, SMEM_GEMM>>>(b2);   // conv2 (profiled slot)
    k_gemm2<1><<<296, 256, SMEM_GEMM>>>(b3);   // conv3
    k_caps_u<<<2500, 256>>>(pcw, pcb);
    k_pass<0><<<625, 256>>>(W);
    k_pass<1><<<625, 256>>>(W);
    k_pass<2><<<625, 256>>>(W);
    k_squash_final<<<32, 128>>>(out);
}

// round 13
// speedup vs baseline: 1.1378x; 1.0894x over previous
#include <cuda_runtime.h>
#include <cuda_fp16.h>
#include <math.h>
#include <cstdint>

// ===========================================================================
//   conv1 -> conv2 (implicit GEMM M=20000,N=256,K=9216)
//   conv3 (K=512) -> u -> fused routing (on-the-fly u_hat, thread-local o)
//   GEMMs: single-term fp16 mma.sync, fp32 accum, BK=64, 3-stage cp.async.
//   Grid 296: 33xM160 + 115xM128 exact tiles, one wave, SM-paired.
// ===========================================================================

__device__ __align__(16) __half g_xpf[32 * 30 * 30 * 256];   // pads stay 0 (static init)
__device__ __align__(16) __half g_zc[20000 * 512];           // [conv1|conv2] fp16
__device__ __align__(16) __half g_w2f[256 * 9216];
__device__ __align__(16) __half g_w3f[256 * 512];
__device__ float g_c3[20000 * 256];
__device__ float g_u[20000 * 256];       // u[n][b*8+o]
__device__ float g_S0[32 * 128];
__device__ float g_S1[32 * 128];
__device__ float g_S2[32 * 128];

// ---------------------------------------------------------------------------
// zero only the atomically-accumulated S arrays (48 KB)
__global__ void k_zeroS() {
    int i = blockIdx.x * 256 + threadIdx.x;
    if (i < 4096) { g_S0[i] = 0.f; g_S1[i] = 0.f; g_S2[i] = 0.f; }
}

// conv1: block = (batch, 5 output rows). w1 taps in registers, x tile in smem.
__global__ void __launch_bounds__(256) k_conv1(const float* __restrict__ x,
                                               const float* __restrict__ w1,
                                               const float* __restrict__ b1) {
    __shared__ float xs[14 * 54];
    int b = blockIdx.x;
    int r0 = blockIdx.y * 5;
    int t = threadIdx.x;

    for (int idx = t; idx < 14 * 54; idx += 256) {
        int row = idx / 54, col = idx % 54;
        xs[idx] = x[b * 2916 + (2 * r0 + row) * 54 + col];
    }
    float wr[36];
#pragma unroll
    for (int j = 0; j < 36; j++) wr[j] = __ldg(&w1[t * 36 + j]);
    float bias = __ldg(&b1[t]);
    __syncthreads();

    for (int pr = 0; pr < 5; pr++) {
        int oh = r0 + pr;
#pragma unroll 5
        for (int ow = 0; ow < 25; ow++) {
            float acc = bias;
#pragma unroll
            for (int kh = 0; kh < 6; kh++)
#pragma unroll
                for (int kw = 0; kw < 6; kw++)
                    acc += xs[(2 * pr + kh) * 54 + 2 * ow + kw] * wr[kh * 6 + kw];
            acc = fmaxf(acc, 0.f);
            __half h = __float2half_rn(acc);
            g_xpf[((b * 30 + oh + 2) * 30 + (ow + 2)) * 256 + t] = h;
            g_zc[(b * 625 + oh * 25 + ow) * 512 + t] = h;
        }
    }
}

// fused weight prep: blocks 0..255 -> conv2 w transpose, 256..767 -> conv3 w
__global__ void k_prep_w(const float* __restrict__ w2,
                         const float* __restrict__ w3) {
    __shared__ float s[256 * 37];
    int bx = blockIdx.x;
    int t = threadIdx.x;
    if (bx < 256) {
        int oc = bx;
        for (int j = 0; j < 36; j++) {
            int idx = t + 256 * j;
            int ic = idx / 36, khw = idx % 36;
            s[ic * 37 + khw] = w2[oc * 9216 + idx];
        }
        __syncthreads();
        for (int j = 0; j < 36; j++) {
            int o = t + 256 * j;
            int khw = o >> 8, ic = o & 255;
            g_w2f[oc * 9216 + o] = __float2half_rn(s[ic * 37 + khw]);
        }
    } else {
        int i = (bx - 256) * 256 + t;
        if (i < 131072) g_w3f[i] = __float2half_rn(w3[i]);
    }
}

// ---------------------------------------------------------------------------
// GEMM helpers
// ---------------------------------------------------------------------------
__device__ __forceinline__ uint32_t smem_u32(const void* p) {
    uint32_t a;
    asm("{ .reg .u64 t; cvta.to.shared.u64 t, %1; cvt.u32.u64 %0, t; }" : "=r"(a) : "l"(p));
    return a;
}
__device__ __forceinline__ void cpa16(uint32_t d, const void* g) {
    asm volatile("cp.async.cg.shared.global [%0], [%1], 16;" :: "r"(d), "l"(g) : "memory");
}
#define CP_COMMIT() asm volatile("cp.async.commit_group;" ::: "memory")
#define CP_WAIT(n)  asm volatile("cp.async.wait_group %0;" :: "n"(n) : "memory")

__device__ __forceinline__ void ldsm4(uint32_t& r0, uint32_t& r1, uint32_t& r2, uint32_t& r3,
                                      uint32_t a) {
    asm volatile("ldmatrix.sync.aligned.m8n8.x4.shared.b16 {%0,%1,%2,%3}, [%4];"
                 : "=r"(r0), "=r"(r1), "=r"(r2), "=r"(r3) : "r"(a));
}
__device__ __forceinline__ void mma16816(float& c0, float& c1, float& c2, float& c3,
                                         uint32_t a0, uint32_t a1, uint32_t a2, uint32_t a3,
                                         uint32_t b0, uint32_t b1) {
    asm volatile("mma.sync.aligned.m16n8k16.row.col.f32.f16.f16.f32 "
                 "{%0,%1,%2,%3}, {%4,%5,%6,%7}, {%8,%9}, {%0,%1,%2,%3};"
                 : "+f"(c0), "+f"(c1), "+f"(c2), "+f"(c3)
                 : "r"(a0), "r"(a1), "r"(a2), "r"(a3), "r"(b0), "r"(b1));
}

// 128B rows, 8x16B chunks, chunk ^= row&7 -> conflict-free cp.async + ldmatrix
__device__ __forceinline__ uint32_t swad(uint32_t region, int row, int chunk) {
    return region + (uint32_t)row * 128u + (uint32_t)((chunk ^ (row & 7)) << 4);
}

// stage: A up to 160x64 fp16 (20480B) | B 128x64 (16384B)
#define OFF_B  20480
#define STGSZ  36864
#define SMEM_GEMM (3 * STGSZ)

template<int MODE>
__global__ void __launch_bounds__(256, 2) k_gemm2(const float* __restrict__ bias) {
    constexpr int K = (MODE == 0) ? 9216 : 512;
    constexpr int S = K / 64;
    extern __shared__ char sm[];
    __shared__ int s_rowbase[160];
    const uint32_t sbase = smem_u32(sm);
    const int tid = threadIdx.x;

    int sslot = blockIdx.x % 148, wave = blockIdx.x / 148;
    int MI, m0, n0;
    if (sslot < 66 && wave == 0) {
        MI = 5; m0 = (sslot >> 1) * 160; n0 = (sslot & 1) * 128;
    } else {
        int j = (wave == 0) ? (sslot - 66) : (82 + sslot);
        MI = 4; m0 = 5280 + (j >> 1) * 128; n0 = (j & 1) * 128;
    }
    const int achunks = MI * 256;          // A rows(MI*32) * 8 chunks

    if (MODE == 0 && tid < 160) {
        int m = min(m0 + tid, 19999);
        int b = m / 625, p = m % 625, oh = p / 25, ow = p % 25;
        s_rowbase[tid] = ((b * 30 + oh) * 30 + ow) * 256;
    }
    __syncthreads();

    const __half* WH = (MODE == 0) ? g_w2f : g_w3f;

    auto issue = [&](int s) {
        int k0 = s * 64;
        uint32_t dbase = sbase + (s % 3) * STGSZ;
        int aoff = 0;
        if (MODE == 0) {
            int khw = k0 >> 8;
            int kh = khw / 6, kw = khw - kh * 6;
            aoff = (kh * 30 + kw) * 256 + (k0 & 255);
        }
#pragma unroll
        for (int j = 0; j < 9; j++) {
            int c = tid + j * 256;
            if (c < achunks) {                   // A region
                int row = c >> 3, kc = c & 7;
                const __half* src;
                if (MODE == 0) src = g_xpf + s_rowbase[row] + aoff + kc * 8;
                else           src = g_zc + (size_t)(m0 + row) * 512 + k0 + kc * 8;
                cpa16(swad(dbase, row, kc), src);
            } else if (c < achunks + 1024) {     // B
                int c2 = c - achunks;
                int row = c2 >> 3, kc = c2 & 7;
                cpa16(swad(dbase + OFF_B, row, kc),
                      WH + (size_t)(n0 + row) * K + k0 + kc * 8);
            }
        }
        CP_COMMIT();
    };

    const int lane = tid & 31, wid = tid >> 5;
    const int wm = (wid & 1) * (MI * 16), wn = (wid >> 1) * 32;
    const int grp = lane >> 2, q = lane & 3;
    const int lrow = lane & 15, lk = lane >> 4;

    float acc[5][4][4];
#pragma unroll
    for (int i = 0; i < 5; i++)
#pragma unroll
        for (int j = 0; j < 4; j++)
#pragma unroll
            for (int c = 0; c < 4; c++) acc[i][j][c] = 0.f;

    issue(0);
    issue(1);

    for (int s = 0; s < S; s++) {
        if (s < S - 1) CP_WAIT(1); else CP_WAIT(0);
        __syncthreads();
        if (s + 2 < S) issue(s + 2);

        uint32_t Ar = sbase + (s % 3) * STGSZ;
        uint32_t Br = Ar + OFF_B;

#pragma unroll
        for (int kk = 0; kk < 4; kk++) {
            int ckc = kk * 2 + lk;
            uint32_t bh[4][2];
#pragma unroll
            for (int p2 = 0; p2 < 2; p2++) {
                int row = wn + p2 * 16 + lrow;
                uint32_t r0, r1, r2, r3;
                ldsm4(r0, r1, r2, r3, swad(Br, row, ckc));
                bh[2 * p2][0] = r0; bh[2 * p2][1] = r2;
                bh[2 * p2 + 1][0] = r1; bh[2 * p2 + 1][1] = r3;
            }
#pragma unroll
            for (int mi = 0; mi < 4; mi++) {
                uint32_t a0, a1, a2, a3;
                ldsm4(a0, a1, a2, a3, swad(Ar, wm + mi * 16 + lrow, ckc));
#pragma unroll
                for (int ni = 0; ni < 4; ni++) {
                    float* c = acc[mi][ni];
                    mma16816(c[0], c[1], c[2], c[3], a0, a1, a2, a3,
                             bh[ni][0], bh[ni][1]);
                }
            }
            if (MI == 5) {
                uint32_t a0, a1, a2, a3;
                ldsm4(a0, a1, a2, a3, swad(Ar, wm + 64 + lrow, ckc));
#pragma unroll
                for (int ni = 0; ni < 4; ni++) {
                    float* c = acc[4][ni];
                    mma16816(c[0], c[1], c[2], c[3], a0, a1, a2, a3,
                             bh[ni][0], bh[ni][1]);
                }
            }
        }
    }
    __syncthreads();

    // epilogue (exact tiles, every row written once)
#pragma unroll
    for (int mi = 0; mi < 5; mi++) {
        if (mi == 4 && MI != 5) break;
#pragma unroll
        for (int ni = 0; ni < 4; ni++) {
            int col = n0 + wn + ni * 8 + 2 * q;
            float bb0 = bias[col], bb1 = bias[col + 1];
            int row0 = m0 + wm + mi * 16 + grp;
            int row1 = row0 + 8;
            float* c = acc[mi][ni];
            if (MODE == 0) {
                float v0 = fmaxf(c[0] + bb0, 0.f), v1 = fmaxf(c[1] + bb1, 0.f);
                __half2 h01; h01.x = __float2half_rn(v0); h01.y = __float2half_rn(v1);
                *(__half2*)&g_zc[(size_t)row0 * 512 + 256 + col] = h01;
                float v2 = fmaxf(c[2] + bb0, 0.f), v3 = fmaxf(c[3] + bb1, 0.f);
                __half2 h23; h23.x = __float2half_rn(v2); h23.y = __float2half_rn(v3);
                *(__half2*)&g_zc[(size_t)row1 * 512 + 256 + col] = h23;
            } else {
                *(float2*)&g_c3[(size_t)row0 * 256 + col] = make_float2(c[0] + bb0, c[1] + bb1);
                *(float2*)&g_c3[(size_t)row1 * 256 + col] = make_float2(c[2] + bb0, c[3] + bb1);
            }
        }
    }
}

// ---------------------------------------------------------------------------
// caps_u, block per hw (625 blocks). All accesses coalesced via smem staging.
// u[g*625+hw][b*8+o] = pcb[n][o] + sum_j c3[b*625+hw][g*8+j] * pcw[n][o*8+j]
// ---------------------------------------------------------------------------
__global__ void __launch_bounds__(256) k_caps_u(const float* __restrict__ pcw,
                                                const float* __restrict__ pcb) {
    __shared__ float sc3[32][260];
    __shared__ float spw[32][68];
    __shared__ float spb[256];
    int hw = blockIdx.x;
    int t = threadIdx.x;
    int b = t >> 3, o = t & 7;

    // stage c3 rows (b=0..31 at this hw), fully coalesced
#pragma unroll
    for (int j = 0; j < 8; j++) {
        int idx = t + j * 256;              // 2048 float4 slots
        int bb = idx >> 6, pos = idx & 63;
        float4 v = __ldg((const float4*)&g_c3[(size_t)(bb * 625 + hw) * 256] + pos);
        *(float4*)&sc3[bb][pos * 4] = v;
    }
    // stage pcw groups (g=0..31)
#pragma unroll
    for (int j = 0; j < 2; j++) {
        int idx = t + j * 256;              // 512 float4 slots
        int g = idx >> 4, pos = idx & 15;
        float4 v = __ldg((const float4*)&pcw[(size_t)(g * 625 + hw) * 64] + pos);
        *(float4*)&spw[g][pos * 4] = v;
    }
    {
        int g = t >> 3, oo = t & 7;
        spb[t] = __ldg(&pcb[(size_t)(g * 625 + hw) * 8 + oo]);
    }
    __syncthreads();

#pragma unroll 4
    for (int g = 0; g < 32; g++) {
        float4 wa = *(float4*)&spw[g][o * 8];
        float4 wb = *(float4*)&spw[g][o * 8 + 4];
        float4 ca = *(float4*)&sc3[b][g * 8];
        float4 cb = *(float4*)&sc3[b][g * 8 + 4];
        float u = spb[g * 8 + o]
                + ca.x * wa.x + ca.y * wa.y + ca.z * wa.z + ca.w * wa.w
                + cb.x * wb.x + cb.y * wb.y + cb.z * wb.z + cb.w * wb.w;
        g_u[(size_t)(g * 625 + hw) * 256 + t] = u;
    }
}

// ---------------------------------------------------------------------------
// Fused routing pass, thread owns (b, e) with all 16 o in registers.
// 592 blocks (4 per SM exactly), per-block n-range [bid*20000/592, ...).
// ---------------------------------------------------------------------------
template<int PASS>
__global__ void __launch_bounds__(256) k_pass(const float* __restrict__ W) {
    __shared__ float sU[34][256];       // 34.8 KB
    __shared__ float sW[4][1056];       // 16.9 KB
    int t = threadIdx.x, wid = t >> 5, lane = t & 31;
    int b = wid * 4 + (lane >> 3);
    int e = lane & 7;
    int bid = blockIdx.x;
    int ns = (bid * 20000) / 592;
    int ne = ((bid + 1) * 20000) / 592;
    int count = ne - ns;                // 33 or 34

    // stage u tile (coalesced)
    for (int idx = t; idx < count * 64; idx += 256) {
        int nn = idx >> 6, pos = idx & 63;
        ((float4*)sU[nn])[pos] = __ldg((const float4*)&g_u[(size_t)(ns + nn) * 256] + pos);
    }

    // thread-local v0/v1 (squash over o is thread-local)
    float vv0[16], vv1[16];
    if (PASS >= 1) {
        float sv[16], n2 = 0.f;
#pragma unroll
        for (int o4 = 0; o4 < 4; o4++) {
            float4 s4 = __ldg((const float4*)&g_S0[b * 128 + e * 16 + o4 * 4]);
            sv[o4 * 4 + 0] = s4.x * 0.125f; sv[o4 * 4 + 1] = s4.y * 0.125f;
            sv[o4 * 4 + 2] = s4.z * 0.125f; sv[o4 * 4 + 3] = s4.w * 0.125f;
        }
#pragma unroll
        for (int o = 0; o < 16; o++) n2 += sv[o] * sv[o];
        float nn = sqrtf(n2);
        float f = (n2 / (1.f + n2)) / (nn + 1e-8f);
#pragma unroll
        for (int o = 0; o < 16; o++) vv0[o] = sv[o] * f;
        if (PASS == 2) {
            float n2b = 0.f;
#pragma unroll
            for (int o4 = 0; o4 < 4; o4++) {
                float4 s4 = __ldg((const float4*)&g_S1[b * 128 + e * 16 + o4 * 4]);
                sv[o4 * 4 + 0] = s4.x; sv[o4 * 4 + 1] = s4.y;
                sv[o4 * 4 + 2] = s4.z; sv[o4 * 4 + 3] = s4.w;
            }
#pragma unroll
            for (int o = 0; o < 16; o++) n2b += sv[o] * sv[o];
            float nnb = sqrtf(n2b);
            float fb = (n2b / (1.f + n2b)) / (nnb + 1e-8f);
#pragma unroll
            for (int o = 0; o < 16; o++) vv1[o] = sv[o] * fb;
        }
    }

    float accS[16];
#pragma unroll
    for (int o = 0; o < 16; o++) accS[o] = 0.f;

    // W stage dest mapping
    int wrem = t & 31;
    int wdst = (t >> 5) * 132 + (wrem >> 1) * 8 + (wrem & 1) * 4;

    __syncthreads();

    for (int g0 = 0; g0 < count; g0 += 4) {
        if (g0) __syncthreads();
#pragma unroll
        for (int j = 0; j < 4; j++) {
            int nl = min(g0 + j, count - 1);
            float4 wv = __ldg((const float4*)&W[(size_t)(ns + nl) * 1024] + t);
            *(float4*)&sW[j][wdst] = wv;
        }
        __syncthreads();

#pragma unroll
        for (int j = 0; j < 4; j++) {
            int nl = g0 + j;
            if (nl >= count) break;
            float4 ua = *(float4*)&sU[nl][b * 8];
            float4 ub = *(float4*)&sU[nl][b * 8 + 4];
            float uh[16];
#pragma unroll
            for (int o = 0; o < 16; o++) {
                float4 wa = *(float4*)&sW[j][e * 132 + o * 8];
                float4 wb = *(float4*)&sW[j][e * 132 + o * 8 + 4];
                uh[o] = ua.x * wa.x + ua.y * wa.y + ua.z * wa.z + ua.w * wa.w
                      + ub.x * wb.x + ub.y * wb.y + ub.z * wb.z + ub.w * wb.w;
            }
            if (PASS == 0) {
#pragma unroll
                for (int o = 0; o < 16; o++) accS[o] += uh[o];
            } else {
                float d = 0.f;
#pragma unroll
                for (int o = 0; o < 16; o++) d += uh[o] * vv0[o];
                if (PASS == 2) {
#pragma unroll
                    for (int o = 0; o < 16; o++) d += uh[o] * vv1[o];
                }
                float m = d;
                m = fmaxf(m, __shfl_xor_sync(0xffffffffu, m, 1));
                m = fmaxf(m, __shfl_xor_sync(0xffffffffu, m, 2));
                m = fmaxf(m, __shfl_xor_sync(0xffffffffu, m, 4));
                float ex = __expf(d - m);
                float Z = ex;
                Z += __shfl_xor_sync(0xffffffffu, Z, 1);
                Z += __shfl_xor_sync(0xffffffffu, Z, 2);
                Z += __shfl_xor_sync(0xffffffffu, Z, 4);
                float c = ex / Z;
#pragma unroll
                for (int o = 0; o < 16; o++) accS[o] += c * uh[o];
            }
        }
    }

    float* Sout = (PASS == 0) ? g_S0 : (PASS == 1) ? g_S1 : g_S2;
#pragma unroll
    for (int o = 0; o < 16; o++)
        atomicAdd(&Sout[b * 128 + e * 16 + o], accS[o]);
}

// final: ||squash(S2)|| = n2*nn / ((1+n2)*(nn+1e-8)) — single reduction
__global__ void k_squash_final(float* __restrict__ out) {
    int b = blockIdx.x, t = threadIdx.x;
    float s = g_S2[b * 128 + t];
    float n2 = s * s;
#pragma unroll
    for (int off = 8; off; off >>= 1)
        n2 += __shfl_xor_sync(0xffffffffu, n2, off);
    float nn = sqrtf(n2);
    if ((t & 15) == 0)
        out[b * 8 + (t >> 4)] = n2 * nn / ((1.f + n2) * (nn + 1e-8f));
}

// ===========================================================================
extern "C" void kernel_launch(void* const* d_in, const int* in_sizes, int n_in,
                              void* d_out, int out_size) {
    const float* x   = (const float*)d_in[0];
    const float* w1  = (const float*)d_in[1];
    const float* b1  = (const float*)d_in[2];
    const float* w2  = (const float*)d_in[3];
    const float* b2  = (const float*)d_in[4];
    const float* w3  = (const float*)d_in[5];
    const float* b3  = (const float*)d_in[6];
    const float* pcw = (const float*)d_in[7];
    const float* pcb = (const float*)d_in[8];
    const float* W   = (const float*)d_in[9];
    float* out = (float*)d_out;

    cudaFuncSetAttribute(k_gemm2<0>, cudaFuncAttributeMaxDynamicSharedMemorySize, SMEM_GEMM);
    cudaFuncSetAttribute(k_gemm2<1>, cudaFuncAttributeMaxDynamicSharedMemorySize, SMEM_GEMM);

    k_zeroS<<<16, 256>>>();
    k_conv1<<<dim3(32, 5), 256>>>(x, w1, b1);
    k_prep_w<<<768, 256>>>(w2, w3);
    k_gemm2<0><<<296, 256, SMEM_GEMM>>>(b2);   // conv2 (profiled slot)
    k_gemm2<1><<<296, 256, SMEM_GEMM>>>(b3);   // conv3
    k_caps_u<<<625, 256>>>(pcw, pcb);
    k_pass<0><<<592, 256>>>(W);
    k_pass<1><<<592, 256>>>(W);
    k_pass<2><<<592, 256>>>(W);
    k_squash_final<<<32, 128>>>(out);
}

// round 15
// speedup vs baseline: 1.2874x; 1.1316x over previous
#include <cuda_runtime.h>
#include <cuda_fp16.h>
#include <math.h>
#include <cstdint>

// ===========================================================================
//   conv1 -> conv2 (implicit GEMM M=20000,N=256,K=9216)
//   conv3 (K=512) -> u -> fused routing (on-the-fly u_hat, fp16 W, hfma2)
//   GEMMs: single-term fp16 mma.sync, fp32 accum, BK=64, 3-stage cp.async.
// ===========================================================================

__device__ __align__(16) __half g_xpf[32 * 30 * 30 * 256];   // pads stay 0 (static init)
__device__ __align__(16) __half g_zc[20000 * 512];
__device__ __align__(16) __half g_w2f[256 * 9216];
__device__ __align__(16) __half g_w3f[256 * 512];
__device__ __align__(16) __half g_Wh[20000 * 1024];          // W fp16, [n][e][i][o]
__device__ float g_c3[20000 * 256];
__device__ float g_u[20000 * 256];
__device__ float g_S0[32 * 128];
__device__ float g_S1[32 * 128];
__device__ float g_S2[32 * 128];

// ---------------------------------------------------------------------------
__global__ void k_zeroS() {
    int i = blockIdx.x * 256 + threadIdx.x;
    if (i < 4096) { g_S0[i] = 0.f; g_S1[i] = 0.f; g_S2[i] = 0.f; }
}

// ---------------------------------------------------------------------------
// fused front: conv1 (160 blocks) | w2 transpose (256) | w3 (512) | W->fp16 (5000)
// ---------------------------------------------------------------------------
__global__ void __launch_bounds__(256) k_front(const float* __restrict__ x,
                                               const float* __restrict__ w1,
                                               const float* __restrict__ b1,
                                               const float* __restrict__ w2,
                                               const float* __restrict__ w3,
                                               const float* __restrict__ Wfull) {
    __shared__ float s[256 * 37];
    int bx = blockIdx.x;
    int t = threadIdx.x;

    if (bx < 160) {
        // ---- conv1: b = bx/5, rows r0..r0+4 ----
        int b = bx / 5, r0 = (bx % 5) * 5;
        float* xs = s;
        for (int idx = t; idx < 14 * 54; idx += 256) {
            int row = idx / 54, col = idx % 54;
            xs[idx] = x[b * 2916 + (2 * r0 + row) * 54 + col];
        }
        float wr[36];
#pragma unroll
        for (int j = 0; j < 36; j++) wr[j] = __ldg(&w1[t * 36 + j]);
        float bias = __ldg(&b1[t]);
        __syncthreads();
        for (int pr = 0; pr < 5; pr++) {
            int oh = r0 + pr;
#pragma unroll 5
            for (int ow = 0; ow < 25; ow++) {
                float acc = bias;
#pragma unroll
                for (int kh = 0; kh < 6; kh++)
#pragma unroll
                    for (int kw = 0; kw < 6; kw++)
                        acc += xs[(2 * pr + kh) * 54 + 2 * ow + kw] * wr[kh * 6 + kw];
                acc = fmaxf(acc, 0.f);
                __half h = __float2half_rn(acc);
                g_xpf[((b * 30 + oh + 2) * 30 + (ow + 2)) * 256 + t] = h;
                g_zc[(b * 625 + oh * 25 + ow) * 512 + t] = h;
            }
        }
    } else if (bx < 416) {
        // ---- conv2 weight transpose: (oc,ic,khw) -> fp16 [oc][khw*256+ic] ----
        int oc = bx - 160;
        for (int j = 0; j < 36; j++) {
            int idx = t + 256 * j;
            int ic = idx / 36, khw = idx % 36;
            s[ic * 37 + khw] = w2[oc * 9216 + idx];
        }
        __syncthreads();
        for (int j = 0; j < 36; j++) {
            int o = t + 256 * j;
            int khw = o >> 8, ic = o & 255;
            g_w2f[oc * 9216 + o] = __float2half_rn(s[ic * 37 + khw]);
        }
    } else if (bx < 928) {
        int i = (bx - 416) * 256 + t;
        if (i < 131072) g_w3f[i] = __float2half_rn(w3[i]);
    } else {
        // ---- W -> fp16, transposed [n][e][i][o], 4 n per block ----
        int n0 = (bx - 928) * 4;
        __half* hb = (__half*)s;
        int f = t * 4;
        int e = f >> 7, rem = f & 127;
        int o = rem >> 3, i0 = rem & 7;      // src flat = e*128 + o*8 + i
#pragma unroll
        for (int nn = 0; nn < 4; nn++) {
            float4 w4 = __ldg((const float4*)&Wfull[(size_t)(n0 + nn) * 1024 + f]);
            int dst = nn * 1024 + e * 128 + i0 * 16 + o;
            hb[dst]      = __float2half_rn(w4.x);
            hb[dst + 16] = __float2half_rn(w4.y);
            hb[dst + 32] = __float2half_rn(w4.z);
            hb[dst + 48] = __float2half_rn(w4.w);
        }
        __syncthreads();
#pragma unroll
        for (int nn = 0; nn < 4; nn++)
            *((uint2*)(g_Wh + (size_t)(n0 + nn) * 1024) + t) =
                *((uint2*)(hb + nn * 1024) + t);
    }
}

// ---------------------------------------------------------------------------
// GEMM helpers
// ---------------------------------------------------------------------------
__device__ __forceinline__ uint32_t smem_u32(const void* p) {
    uint32_t a;
    asm("{ .reg .u64 t; cvta.to.shared.u64 t, %1; cvt.u32.u64 %0, t; }" : "=r"(a) : "l"(p));
    return a;
}
__device__ __forceinline__ void cpa16(uint32_t d, const void* g) {
    asm volatile("cp.async.cg.shared.global [%0], [%1], 16;" :: "r"(d), "l"(g) : "memory");
}
#define CP_COMMIT() asm volatile("cp.async.commit_group;" ::: "memory")
#define CP_WAIT(n)  asm volatile("cp.async.wait_group %0;" :: "n"(n) : "memory")

__device__ __forceinline__ void ldsm4(uint32_t& r0, uint32_t& r1, uint32_t& r2, uint32_t& r3,
                                      uint32_t a) {
    asm volatile("ldmatrix.sync.aligned.m8n8.x4.shared.b16 {%0,%1,%2,%3}, [%4];"
                 : "=r"(r0), "=r"(r1), "=r"(r2), "=r"(r3) : "r"(a));
}
__device__ __forceinline__ void mma16816(float& c0, float& c1, float& c2, float& c3,
                                         uint32_t a0, uint32_t a1, uint32_t a2, uint32_t a3,
                                         uint32_t b0, uint32_t b1) {
    asm volatile("mma.sync.aligned.m16n8k16.row.col.f32.f16.f16.f32 "
                 "{%0,%1,%2,%3}, {%4,%5,%6,%7}, {%8,%9}, {%0,%1,%2,%3};"
                 : "+f"(c0), "+f"(c1), "+f"(c2), "+f"(c3)
                 : "r"(a0), "r"(a1), "r"(a2), "r"(a3), "r"(b0), "r"(b1));
}

__device__ __forceinline__ uint32_t swad(uint32_t region, int row, int chunk) {
    return region + (uint32_t)row * 128u + (uint32_t)((chunk ^ (row & 7)) << 4);
}

#define OFF_B  20480
#define STGSZ  36864
#define SMEM_GEMM (3 * STGSZ)

template<int MODE>
__global__ void __launch_bounds__(256, 2) k_gemm2(const float* __restrict__ bias) {
    constexpr int K = (MODE == 0) ? 9216 : 512;
    constexpr int S = K / 64;
    extern __shared__ char sm[];
    __shared__ int s_rowbase[160];
    const uint32_t sbase = smem_u32(sm);
    const int tid = threadIdx.x;

    int sslot = blockIdx.x % 148, wave = blockIdx.x / 148;
    int MI, m0, n0;
    if (sslot < 66 && wave == 0) {
        MI = 5; m0 = (sslot >> 1) * 160; n0 = (sslot & 1) * 128;
    } else {
        int j = (wave == 0) ? (sslot - 66) : (82 + sslot);
        MI = 4; m0 = 5280 + (j >> 1) * 128; n0 = (j & 1) * 128;
    }
    const int achunks = MI * 256;

    if (MODE == 0 && tid < 160) {
        int m = min(m0 + tid, 19999);
        int b = m / 625, p = m % 625, oh = p / 25, ow = p % 25;
        s_rowbase[tid] = ((b * 30 + oh) * 30 + ow) * 256;
    }
    __syncthreads();

    const __half* WH = (MODE == 0) ? g_w2f : g_w3f;

    auto issue = [&](int s) {
        int k0 = s * 64;
        uint32_t dbase = sbase + (s % 3) * STGSZ;
        int aoff = 0;
        if (MODE == 0) {
            int khw = k0 >> 8;
            int kh = khw / 6, kw = khw - kh * 6;
            aoff = (kh * 30 + kw) * 256 + (k0 & 255);
        }
#pragma unroll
        for (int j = 0; j < 9; j++) {
            int c = tid + j * 256;
            if (c < achunks) {
                int row = c >> 3, kc = c & 7;
                const __half* src;
                if (MODE == 0) src = g_xpf + s_rowbase[row] + aoff + kc * 8;
                else           src = g_zc + (size_t)(m0 + row) * 512 + k0 + kc * 8;
                cpa16(swad(dbase, row, kc), src);
            } else if (c < achunks + 1024) {
                int c2 = c - achunks;
                int row = c2 >> 3, kc = c2 & 7;
                cpa16(swad(dbase + OFF_B, row, kc),
                      WH + (size_t)(n0 + row) * K + k0 + kc * 8);
            }
        }
        CP_COMMIT();
    };

    const int lane = tid & 31, wid = tid >> 5;
    const int wm = (wid & 1) * (MI * 16), wn = (wid >> 1) * 32;
    const int grp = lane >> 2, q = lane & 3;
    const int lrow = lane & 15, lk = lane >> 4;

    float acc[5][4][4];
#pragma unroll
    for (int i = 0; i < 5; i++)
#pragma unroll
        for (int j = 0; j < 4; j++)
#pragma unroll
            for (int c = 0; c < 4; c++) acc[i][j][c] = 0.f;

    issue(0);
    issue(1);

    for (int s = 0; s < S; s++) {
        if (s < S - 1) CP_WAIT(1); else CP_WAIT(0);
        __syncthreads();
        if (s + 2 < S) issue(s + 2);

        uint32_t Ar = sbase + (s % 3) * STGSZ;
        uint32_t Br = Ar + OFF_B;

#pragma unroll
        for (int kk = 0; kk < 4; kk++) {
            int ckc = kk * 2 + lk;
            uint32_t bh[4][2];
#pragma unroll
            for (int p2 = 0; p2 < 2; p2++) {
                int row = wn + p2 * 16 + lrow;
                uint32_t r0, r1, r2, r3;
                ldsm4(r0, r1, r2, r3, swad(Br, row, ckc));
                bh[2 * p2][0] = r0; bh[2 * p2][1] = r2;
                bh[2 * p2 + 1][0] = r1; bh[2 * p2 + 1][1] = r3;
            }
#pragma unroll
            for (int mi = 0; mi < 4; mi++) {
                uint32_t a0, a1, a2, a3;
                ldsm4(a0, a1, a2, a3, swad(Ar, wm + mi * 16 + lrow, ckc));
#pragma unroll
                for (int ni = 0; ni < 4; ni++) {
                    float* c = acc[mi][ni];
                    mma16816(c[0], c[1], c[2], c[3], a0, a1, a2, a3,
                             bh[ni][0], bh[ni][1]);
                }
            }
            if (MI == 5) {
                uint32_t a0, a1, a2, a3;
                ldsm4(a0, a1, a2, a3, swad(Ar, wm + 64 + lrow, ckc));
#pragma unroll
                for (int ni = 0; ni < 4; ni++) {
                    float* c = acc[4][ni];
                    mma16816(c[0], c[1], c[2], c[3], a0, a1, a2, a3,
                             bh[ni][0], bh[ni][1]);
                }
            }
        }
    }
    __syncthreads();

#pragma unroll
    for (int mi = 0; mi < 5; mi++) {
        if (mi == 4 && MI != 5) break;
#pragma unroll
        for (int ni = 0; ni < 4; ni++) {
            int col = n0 + wn + ni * 8 + 2 * q;
            float bb0 = bias[col], bb1 = bias[col + 1];
            int row0 = m0 + wm + mi * 16 + grp;
            int row1 = row0 + 8;
            float* c = acc[mi][ni];
            if (MODE == 0) {
                float v0 = fmaxf(c[0] + bb0, 0.f), v1 = fmaxf(c[1] + bb1, 0.f);
                __half2 h01; h01.x = __float2half_rn(v0); h01.y = __float2half_rn(v1);
                *(__half2*)&g_zc[(size_t)row0 * 512 + 256 + col] = h01;
                float v2 = fmaxf(c[2] + bb0, 0.f), v3 = fmaxf(c[3] + bb1, 0.f);
                __half2 h23; h23.x = __float2half_rn(v2); h23.y = __float2half_rn(v3);
                *(__half2*)&g_zc[(size_t)row1 * 512 + 256 + col] = h23;
            } else {
                *(float2*)&g_c3[(size_t)row0 * 256 + col] = make_float2(c[0] + bb0, c[1] + bb1);
                *(float2*)&g_c3[(size_t)row1 * 256 + col] = make_float2(c[2] + bb0, c[3] + bb1);
            }
        }
    }
}

// ---------------------------------------------------------------------------
// caps_u, block per hw (625 blocks), smem-staged, fully coalesced.
// ---------------------------------------------------------------------------
__global__ void __launch_bounds__(256) k_caps_u(const float* __restrict__ pcw,
                                                const float* __restrict__ pcb) {
    __shared__ float sc3[32][260];
    __shared__ float spw[32][68];
    __shared__ float spb[256];
    int hw = blockIdx.x;
    int t = threadIdx.x;
    int b = t >> 3, o = t & 7;

#pragma unroll
    for (int j = 0; j < 8; j++) {
        int idx = t + j * 256;
        int bb = idx >> 6, pos = idx & 63;
        float4 v = __ldg((const float4*)&g_c3[(size_t)(bb * 625 + hw) * 256] + pos);
        *(float4*)&sc3[bb][pos * 4] = v;
    }
#pragma unroll
    for (int j = 0; j < 2; j++) {
        int idx = t + j * 256;
        int g = idx >> 4, pos = idx & 15;
        float4 v = __ldg((const float4*)&pcw[(size_t)(g * 625 + hw) * 64] + pos);
        *(float4*)&spw[g][pos * 4] = v;
    }
    {
        int g = t >> 3, oo = t & 7;
        spb[t] = __ldg(&pcb[(size_t)(g * 625 + hw) * 8 + oo]);
    }
    __syncthreads();

#pragma unroll 4
    for (int g = 0; g < 32; g++) {
        float4 wa = *(float4*)&spw[g][o * 8];
        float4 wb = *(float4*)&spw[g][o * 8 + 4];
        float4 ca = *(float4*)&sc3[b][g * 8];
        float4 cb = *(float4*)&sc3[b][g * 8 + 4];
        float u = spb[g * 8 + o]
                + ca.x * wa.x + ca.y * wa.y + ca.z * wa.z + ca.w * wa.w
                + cb.x * wb.x + cb.y * wb.y + cb.z * wb.z + cb.w * wb.w;
        g_u[(size_t)(g * 625 + hw) * 256 + t] = u;
    }
}

// ---------------------------------------------------------------------------
// Fused routing pass, fp16 W (hfma2 over o-pairs). Thread owns (b, e).
// 592 blocks, per-block n range via (bid*20000)/592.
// ---------------------------------------------------------------------------
template<int PASS>
__global__ void __launch_bounds__(256) k_pass(int dummy) {
    __shared__ float sU[34][256];        // 34.8 KB
    __shared__ __half sW[4][1088];       // 8.5 KB  ([j][e*136 + i*16 + o])
    int t = threadIdx.x, wid = t >> 5, lane = t & 31;
    int b = wid * 4 + (lane >> 3);
    int e = lane & 7;
    int bid = blockIdx.x;
    int ns = (bid * 20000) / 592;
    int ne = ((bid + 1) * 20000) / 592;
    int count = ne - ns;

    for (int idx = t; idx < count * 64; idx += 256) {
        int nn = idx >> 6, pos = idx & 63;
        ((float4*)sU[nn])[pos] = __ldg((const float4*)&g_u[(size_t)(ns + nn) * 256] + pos);
    }

    float vv0[16], vv1[16];
    if (PASS >= 1) {
        float sv[16], n2 = 0.f;
#pragma unroll
        for (int o4 = 0; o4 < 4; o4++) {
            float4 s4 = __ldg((const float4*)&g_S0[b * 128 + e * 16 + o4 * 4]);
            sv[o4 * 4 + 0] = s4.x * 0.125f; sv[o4 * 4 + 1] = s4.y * 0.125f;
            sv[o4 * 4 + 2] = s4.z * 0.125f; sv[o4 * 4 + 3] = s4.w * 0.125f;
        }
#pragma unroll
        for (int o = 0; o < 16; o++) n2 += sv[o] * sv[o];
        float nn = sqrtf(n2);
        float f = (n2 / (1.f + n2)) / (nn + 1e-8f);
#pragma unroll
        for (int o = 0; o < 16; o++) vv0[o] = sv[o] * f;
        if (PASS == 2) {
            float n2b = 0.f;
#pragma unroll
            for (int o4 = 0; o4 < 4; o4++) {
                float4 s4 = __ldg((const float4*)&g_S1[b * 128 + e * 16 + o4 * 4]);
                sv[o4 * 4 + 0] = s4.x; sv[o4 * 4 + 1] = s4.y;
                sv[o4 * 4 + 2] = s4.z; sv[o4 * 4 + 3] = s4.w;
            }
#pragma unroll
            for (int o = 0; o < 16; o++) n2b += sv[o] * sv[o];
            float nnb = sqrtf(n2b);
            float fb = (n2b / (1.f + n2b)) / (nnb + 1e-8f);
#pragma unroll
            for (int o = 0; o < 16; o++) vv1[o] = sv[o] * fb;
        }
    }

    float accS[16];
#pragma unroll
    for (int o = 0; o < 16; o++) accS[o] = 0.f;

    // W stage dest mapping: thread copies uint2 (4 halfs) at h-offset t*4
    int se = t >> 5, srem = (t * 4) & 127;
    int si = srem >> 4, so = srem & 15;
    int wdst = se * 136 + si * 16 + so;
    int eoff = e * 136;

    __syncthreads();

    for (int g0 = 0; g0 < count; g0 += 4) {
        if (g0) __syncthreads();
#pragma unroll
        for (int j = 0; j < 4; j++) {
            int nl = min(g0 + j, count - 1);
            uint2 wv = __ldg((const uint2*)(g_Wh + (size_t)(ns + nl) * 1024) + t);
            *(uint2*)&sW[j][wdst] = wv;
        }
        __syncthreads();

#pragma unroll
        for (int j = 0; j < 4; j++) {
            int nl = g0 + j;
            if (nl >= count) break;
            float4 ua = *(float4*)&sU[nl][b * 8];
            float4 ub = *(float4*)&sU[nl][b * 8 + 4];
            __half2 u2[8];
            u2[0] = __float2half2_rn(ua.x); u2[1] = __float2half2_rn(ua.y);
            u2[2] = __float2half2_rn(ua.z); u2[3] = __float2half2_rn(ua.w);
            u2[4] = __float2half2_rn(ub.x); u2[5] = __float2half2_rn(ub.y);
            u2[6] = __float2half2_rn(ub.z); u2[7] = __float2half2_rn(ub.w);

            __half2 uh2[8];
#pragma unroll
            for (int p = 0; p < 8; p++) uh2[p] = __float2half2_rn(0.f);
#pragma unroll
            for (int i = 0; i < 8; i++) {
                uint4 ra = *(uint4*)&sW[j][eoff + i * 16];      // o = 0..7
                uint4 rb = *(uint4*)&sW[j][eoff + i * 16 + 8];  // o = 8..15
                __half2* pa = (__half2*)&ra;
                __half2* pb = (__half2*)&rb;
                uh2[0] = __hfma2(u2[i], pa[0], uh2[0]);
                uh2[1] = __hfma2(u2[i], pa[1], uh2[1]);
                uh2[2] = __hfma2(u2[i], pa[2], uh2[2]);
                uh2[3] = __hfma2(u2[i], pa[3], uh2[3]);
                uh2[4] = __hfma2(u2[i], pb[0], uh2[4]);
                uh2[5] = __hfma2(u2[i], pb[1], uh2[5]);
                uh2[6] = __hfma2(u2[i], pb[2], uh2[6]);
                uh2[7] = __hfma2(u2[i], pb[3], uh2[7]);
            }
            float uhf[16];
#pragma unroll
            for (int p = 0; p < 8; p++) {
                float2 f2 = __half22float2(uh2[p]);
                uhf[2 * p] = f2.x; uhf[2 * p + 1] = f2.y;
            }

            if (PASS == 0) {
#pragma unroll
                for (int o = 0; o < 16; o++) accS[o] += uhf[o];
            } else {
                float d = 0.f;
#pragma unroll
                for (int o = 0; o < 16; o++) d += uhf[o] * vv0[o];
                if (PASS == 2) {
#pragma unroll
                    for (int o = 0; o < 16; o++) d += uhf[o] * vv1[o];
                }
                float m = d;
                m = fmaxf(m, __shfl_xor_sync(0xffffffffu, m, 1));
                m = fmaxf(m, __shfl_xor_sync(0xffffffffu, m, 2));
                m = fmaxf(m, __shfl_xor_sync(0xffffffffu, m, 4));
                float ex = __expf(d - m);
                float Z = ex;
                Z += __shfl_xor_sync(0xffffffffu, Z, 1);
                Z += __shfl_xor_sync(0xffffffffu, Z, 2);
                Z += __shfl_xor_sync(0xffffffffu, Z, 4);
                float c = ex / Z;
#pragma unroll
                for (int o = 0; o < 16; o++) accS[o] += c * uhf[o];
            }
        }
    }

    float* Sout = (PASS == 0) ? g_S0 : (PASS == 1) ? g_S1 : g_S2;
#pragma unroll
    for (int o = 0; o < 16; o++)
        atomicAdd(&Sout[b * 128 + e * 16 + o], accS[o]);
}

// final
__global__ void k_squash_final(float* __restrict__ out) {
    int b = blockIdx.x, t = threadIdx.x;
    float s = g_S2[b * 128 + t];
    float n2 = s * s;
#pragma unroll
    for (int off = 8; off; off >>= 1)
        n2 += __shfl_xor_sync(0xffffffffu, n2, off);
    float nn = sqrtf(n2);
    if ((t & 15) == 0)
        out[b * 8 + (t >> 4)] = n2 * nn / ((1.f + n2) * (nn + 1e-8f));
}

// ===========================================================================
extern "C" void kernel_launch(void* const* d_in, const int* in_sizes, int n_in,
                              void* d_out, int out_size) {
    const float* x   = (const float*)d_in[0];
    const float* w1  = (const float*)d_in[1];
    const float* b1  = (const float*)d_in[2];
    const float* w2  = (const float*)d_in[3];
    const float* b2  = (const float*)d_in[4];
    const float* w3  = (const float*)d_in[5];
    const float* b3  = (const float*)d_in[6];
    const float* pcw = (const float*)d_in[7];
    const float* pcb = (const float*)d_in[8];
    const float* W   = (const float*)d_in[9];
    float* out = (float*)d_out;

    cudaFuncSetAttribute(k_gemm2<0>, cudaFuncAttributeMaxDynamicSharedMemorySize, SMEM_GEMM);
    cudaFuncSetAttribute(k_gemm2<1>, cudaFuncAttributeMaxDynamicSharedMemorySize, SMEM_GEMM);

    k_zeroS<<<16, 256>>>();
    k_front<<<5928, 256>>>(x, w1, b1, w2, w3, W);
    k_gemm2<0><<<296, 256, SMEM_GEMM>>>(b2);   // conv2 (profiled slot)
    k_gemm2<1><<<296, 256, SMEM_GEMM>>>(b3);   // conv3
    k_caps_u<<<625, 256>>>(pcw, pcb);
    k_pass<0><<<592, 256>>>(0);
    k_pass<1><<<592, 256>>>(0);
    k_pass<2><<<592, 256>>>(0);
    k_squash_final<<<32, 128>>>(out);
}